// round 1
// baseline (speedup 1.0000x reference)
#include <cuda_runtime.h>
#include <cstddef>

#define N_NODES 50000
#define DIN 128
#define DHID 256

// ---- scratch (static device globals; no allocation allowed) ----
__device__ float g_deg[N_NODES];              // degree, then 1/max(deg,1)
__device__ float g_agg[N_NODES * DIN];        // 128-wide scatter accumulator (reused both layers)
__device__ float g_h[N_NODES * DHID];         // layer-1 output
__device__ float g_pq[N_NODES * DHID];        // [p | q] = h @ [W2l;W2r]^T

// ---------------------------------------------------------------------------
__global__ void zero_kernel(float4* __restrict__ p, int n4) {
    int i = blockIdx.x * blockDim.x + threadIdx.x;
    if (i < n4) p[i] = make_float4(0.f, 0.f, 0.f, 0.f);
}

__global__ void deg_kernel(const int* __restrict__ dst, int E, float* __restrict__ deg) {
    int i = blockIdx.x * blockDim.x + threadIdx.x;
    if (i < E) atomicAdd(&deg[dst[i]], 1.0f);
}

__global__ void rdeg_kernel(float* __restrict__ deg) {
    int i = blockIdx.x * blockDim.x + threadIdx.x;
    if (i < N_NODES) deg[i] = 1.0f / fmaxf(deg[i], 1.0f);
}

// One warp per edge: gather 128 contiguous floats from feat[src] (ld = row stride),
// vector-atomic-add into agg[dst] (always 128 wide).
__global__ void scatter_kernel(const float* __restrict__ feat, int ld,
                               const int* __restrict__ src,
                               const int* __restrict__ dst,
                               float* __restrict__ agg, int E) {
    int e = blockIdx.x * (blockDim.x >> 5) + (threadIdx.x >> 5);
    if (e >= E) return;
    int lane = threadIdx.x & 31;
    int s = __ldg(src + e);
    int d = __ldg(dst + e);
    float4 v = __ldg(reinterpret_cast<const float4*>(feat + (size_t)s * ld) + lane);
    float* p = agg + (size_t)d * DIN + lane * 4;
    asm volatile("red.global.add.v4.f32 [%0], {%1,%2,%3,%4};"
                 :: "l"(p), "f"(v.x), "f"(v.y), "f"(v.z), "f"(v.w)
                 : "memory");
}

// ---------------------------------------------------------------------------
// Tiled fp32 GEMM, C[N, 256] = A[N, 256] @ B[256, 256]^T (B rows K-contiguous).
// MODE 0 (layer 1): A(row,k) = k<128 ? agg[row,k]*rdeg[row] : X[row,k-128]
//                   B(j,k)   = k<128 ? W1l[j,k]             : W1r[j,k-128]
//                   epilogue: relu(acc + b1[j]) -> C (ld 256)
// MODE 1 (layer 2): A(row,k) = H[row,k]  (ld 256)
//                   B(j,k)   = j<128 ? W2l[j,k] : W2r[j-128,k]  (ld 256)
//                   epilogue: plain store -> C (ld 256)
template <int MODE>
__global__ __launch_bounds__(256)
void gemm_kernel(const float* __restrict__ A0,   // MODE0: agg ; MODE1: h
                 const float* __restrict__ A2,   // MODE0: x   ; MODE1: unused
                 const float* __restrict__ Wl,
                 const float* __restrict__ Wr,
                 const float* __restrict__ bias, // MODE0: b1  ; MODE1: unused
                 const float* __restrict__ rdeg, // MODE0 only
                 float* __restrict__ C) {
    constexpr int BK = 16;
    constexpr int LDS = 132;   // +4 pad: 2-way max store conflict, 16B-aligned rows (132*4=528)
    __shared__ float As[BK][LDS];
    __shared__ float Bs[BK][LDS];

    const int tid  = threadIdx.x;
    const int row0 = blockIdx.x * 128;
    const int col0 = blockIdx.y * 128;
    const int m0   = (tid >> 4) * 8;
    const int n0   = (tid & 15) * 8;

    float acc[8][8];
#pragma unroll
    for (int i = 0; i < 8; i++)
#pragma unroll
        for (int j = 0; j < 8; j++) acc[i][j] = 0.f;

    for (int kt = 0; kt < 256; kt += BK) {
        // ---- load tiles (512 float4 groups each, 2 per thread) ----
#pragma unroll
        for (int it = 0; it < 2; it++) {
            int g  = tid + it * 256;
            int r  = g >> 2;            // 0..127
            int kq = (g & 3) << 2;      // 0,4,8,12
            int k  = kt + kq;

            // A tile
            float4 va = make_float4(0.f, 0.f, 0.f, 0.f);
            int grow = row0 + r;
            if (grow < N_NODES) {
                if (MODE == 0) {
                    if (k < DIN) {
                        va = *reinterpret_cast<const float4*>(A0 + (size_t)grow * DIN + k);
                        float rd = rdeg[grow];
                        va.x *= rd; va.y *= rd; va.z *= rd; va.w *= rd;
                    } else {
                        va = *reinterpret_cast<const float4*>(A2 + (size_t)grow * DIN + (k - DIN));
                    }
                } else {
                    va = *reinterpret_cast<const float4*>(A0 + (size_t)grow * DHID + k);
                }
            }
            As[kq + 0][r] = va.x; As[kq + 1][r] = va.y;
            As[kq + 2][r] = va.z; As[kq + 3][r] = va.w;

            // B tile
            int j = col0 + r;   // always < 256
            float4 vb;
            if (MODE == 0) {
                vb = (k < DIN)
                   ? *reinterpret_cast<const float4*>(Wl + (size_t)j * DIN + k)
                   : *reinterpret_cast<const float4*>(Wr + (size_t)j * DIN + (k - DIN));
            } else {
                vb = (j < 128)
                   ? *reinterpret_cast<const float4*>(Wl + (size_t)j * DHID + k)
                   : *reinterpret_cast<const float4*>(Wr + (size_t)(j - 128) * DHID + k);
            }
            Bs[kq + 0][r] = vb.x; Bs[kq + 1][r] = vb.y;
            Bs[kq + 2][r] = vb.z; Bs[kq + 3][r] = vb.w;
        }
        __syncthreads();

        // ---- compute ----
#pragma unroll
        for (int kk = 0; kk < BK; kk++) {
            float a[8], b[8];
            *reinterpret_cast<float4*>(a)     = *reinterpret_cast<const float4*>(&As[kk][m0]);
            *reinterpret_cast<float4*>(a + 4) = *reinterpret_cast<const float4*>(&As[kk][m0 + 4]);
            *reinterpret_cast<float4*>(b)     = *reinterpret_cast<const float4*>(&Bs[kk][n0]);
            *reinterpret_cast<float4*>(b + 4) = *reinterpret_cast<const float4*>(&Bs[kk][n0 + 4]);
#pragma unroll
            for (int i = 0; i < 8; i++)
#pragma unroll
                for (int j = 0; j < 8; j++) acc[i][j] += a[i] * b[j];
        }
        __syncthreads();
    }

    // ---- epilogue ----
#pragma unroll
    for (int i = 0; i < 8; i++) {
        int row = row0 + m0 + i;
        if (row >= N_NODES) break;
#pragma unroll
        for (int jj = 0; jj < 8; jj += 4) {
            int col = col0 + n0 + jj;
            float4 v = make_float4(acc[i][jj], acc[i][jj + 1], acc[i][jj + 2], acc[i][jj + 3]);
            if (MODE == 0) {
                float4 bb = *reinterpret_cast<const float4*>(bias + col);
                v.x = fmaxf(v.x + bb.x, 0.f);
                v.y = fmaxf(v.y + bb.y, 0.f);
                v.z = fmaxf(v.z + bb.z, 0.f);
                v.w = fmaxf(v.w + bb.w, 0.f);
            }
            *reinterpret_cast<float4*>(C + (size_t)row * DHID + col) = v;
        }
    }
}

// out[n, :] = agg[n, :] * rdeg[n] + b2 + pq[n, 128:256]
__global__ void final_kernel(const float* __restrict__ agg,
                             const float* __restrict__ pq,
                             const float* __restrict__ rdeg,
                             const float* __restrict__ b2,
                             float* __restrict__ out) {
    int t = blockIdx.x * blockDim.x + threadIdx.x;
    if (t >= N_NODES * 32) return;
    int row = t >> 5;
    int q   = (t & 31) * 4;
    float rd = rdeg[row];
    float4 a  = *reinterpret_cast<const float4*>(agg + (size_t)row * DIN + q);
    float4 qv = *reinterpret_cast<const float4*>(pq + (size_t)row * DHID + 128 + q);
    float4 bb = *reinterpret_cast<const float4*>(b2 + q);
    float4 o;
    o.x = a.x * rd + qv.x + bb.x;
    o.y = a.y * rd + qv.y + bb.y;
    o.z = a.z * rd + qv.z + bb.z;
    o.w = a.w * rd + qv.w + bb.w;
    *reinterpret_cast<float4*>(out + (size_t)row * DIN + q) = o;
}

// ---------------------------------------------------------------------------
extern "C" void kernel_launch(void* const* d_in, const int* in_sizes, int n_in,
                              void* d_out, int out_size) {
    const float* x   = (const float*)d_in[0];
    const int*   ei  = (const int*)d_in[1];
    const float* W1l = (const float*)d_in[2];
    const float* b1  = (const float*)d_in[3];
    const float* W1r = (const float*)d_in[4];
    const float* W2l = (const float*)d_in[5];
    const float* b2  = (const float*)d_in[6];
    const float* W2r = (const float*)d_in[7];
    float* out = (float*)d_out;

    const int E = in_sizes[1] / 2;
    const int* src = ei;
    const int* dst = ei + E;

    float *deg, *agg, *h, *pq;
    cudaGetSymbolAddress((void**)&deg, g_deg);
    cudaGetSymbolAddress((void**)&agg, g_agg);
    cudaGetSymbolAddress((void**)&h,   g_h);
    cudaGetSymbolAddress((void**)&pq,  g_pq);

    const int AGG4 = N_NODES * DIN / 4;

    // degree + inverse
    zero_kernel<<<(N_NODES / 4 + 255) / 256, 256>>>((float4*)deg, N_NODES / 4);
    zero_kernel<<<(AGG4 + 255) / 256, 256>>>((float4*)agg, AGG4);
    deg_kernel<<<(E + 255) / 256, 256>>>(dst, E, deg);
    rdeg_kernel<<<(N_NODES + 255) / 256, 256>>>(deg);

    // layer 1: agg = sum_{e} x[src], h = relu([agg*rdeg | x] @ [W1l|W1r]^T + b1)
    scatter_kernel<<<(E + 7) / 8, 256>>>(x, DIN, src, dst, agg, E);
    gemm_kernel<0><<<dim3((N_NODES + 127) / 128, 2), 256>>>(agg, x, W1l, W1r, b1, deg, h);

    // layer 2: [p|q] = h @ [W2l;W2r]^T ; agg = sum_{e} p[src] ; out = agg*rdeg + b2 + q
    gemm_kernel<1><<<dim3((N_NODES + 127) / 128, 2), 256>>>(h, nullptr, W2l, W2r, nullptr, nullptr, pq);
    zero_kernel<<<(AGG4 + 255) / 256, 256>>>((float4*)agg, AGG4);
    scatter_kernel<<<(E + 7) / 8, 256>>>(pq, DHID, src, dst, agg, E);
    final_kernel<<<(N_NODES * 32 + 255) / 256, 256>>>(agg, pq, deg, b2, out);
}

// round 3
// speedup vs baseline: 1.2410x; 1.2410x over previous
#include <cuda_runtime.h>
#include <cuda_bf16.h>
#include <cstdint>
#include <cstddef>

#define N_NODES 50000
#define DIN 128
#define DHID 256

// ---- scratch (static device globals; no allocation allowed) ----
__device__ float g_deg[N_NODES];
__device__ float g_agg[N_NODES * DIN];
__device__ float g_h[N_NODES * DHID];
__device__ float g_pq[N_NODES * DHID];

// ---------------------------------------------------------------------------
// small helper kernels
// ---------------------------------------------------------------------------
__global__ void zero_kernel(float4* __restrict__ p, int n4) {
    int i = blockIdx.x * blockDim.x + threadIdx.x;
    if (i < n4) p[i] = make_float4(0.f, 0.f, 0.f, 0.f);
}

__global__ void deg_kernel(const int* __restrict__ dst, int E, float* __restrict__ deg) {
    int i = blockIdx.x * blockDim.x + threadIdx.x;
    if (i < E) atomicAdd(&deg[dst[i]], 1.0f);
}

__global__ void rdeg_kernel(float* __restrict__ deg) {
    int i = blockIdx.x * blockDim.x + threadIdx.x;
    if (i < N_NODES) deg[i] = 1.0f / fmaxf(deg[i], 1.0f);
}

// One warp per edge: gather 128 floats from feat[src] (ld = row stride),
// vector-atomic-add into agg[dst] (128 wide).
__global__ void scatter_kernel(const float* __restrict__ feat, int ld,
                               const int* __restrict__ src,
                               const int* __restrict__ dst,
                               float* __restrict__ agg, int E) {
    int e = blockIdx.x * (blockDim.x >> 5) + (threadIdx.x >> 5);
    if (e >= E) return;
    int lane = threadIdx.x & 31;
    int s = __ldg(src + e);
    int d = __ldg(dst + e);
    float4 v = __ldg(reinterpret_cast<const float4*>(feat + (size_t)s * ld) + lane);
    float* p = agg + (size_t)d * DIN + lane * 4;
    asm volatile("red.global.add.v4.f32 [%0], {%1,%2,%3,%4};"
                 :: "l"(p), "f"(v.x), "f"(v.y), "f"(v.z), "f"(v.w)
                 : "memory");
}

// out[n, :] = agg[n, :] * rdeg[n] + b2 + pq[n, 128:256]
__global__ void final_kernel(const float* __restrict__ agg,
                             const float* __restrict__ pq,
                             const float* __restrict__ rdeg,
                             const float* __restrict__ b2,
                             float* __restrict__ out) {
    int t = blockIdx.x * blockDim.x + threadIdx.x;
    if (t >= N_NODES * 32) return;
    int row = t >> 5;
    int q = (t & 31) * 4;
    float rd = rdeg[row];
    float4 a  = *reinterpret_cast<const float4*>(agg + (size_t)row * DIN + q);
    float4 qv = *reinterpret_cast<const float4*>(pq + (size_t)row * DHID + 128 + q);
    float4 bb = *reinterpret_cast<const float4*>(b2 + q);
    float4 o;
    o.x = a.x * rd + qv.x + bb.x;
    o.y = a.y * rd + qv.y + bb.y;
    o.z = a.z * rd + qv.z + bb.z;
    o.w = a.w * rd + qv.w + bb.w;
    *reinterpret_cast<float4*>(out + (size_t)row * DIN + q) = o;
}

// ---------------------------------------------------------------------------
// bf16-split tensor-core GEMM via mma.sync (arch-neutral PTX, HMMA pipe)
// C[N_NODES, 256] = A[N_NODES, 256] @ B[256, 256]^T
// split: A = Ah + Al, B = Bh + Bl (bf16), C ~= AhBh + AhBl + AlBh
// MODE 0 (layer 1): A = [agg*rdeg | x], B = [W1l | W1r] (K concat), relu(+b1)
// MODE 1 (layer 2): A = h (ld 256),     B rows = [W2l ; W2r] (N concat)
// Block tile: 128(M) x 128(N), k-chunk 32. 8 warps, each 64x32.
// ---------------------------------------------------------------------------
#define LDA 40   // bf16 elems per smem row (32 + 8 pad -> conflict-free frag loads)

__device__ __forceinline__ uint32_t pack_bf16(float x, float y) {
    __nv_bfloat162 t = __float22bfloat162_rn(make_float2(x, y));
    return *reinterpret_cast<uint32_t*>(&t);
}

__device__ __forceinline__ void mma_bf16(float* c, const uint32_t* a, const uint32_t* b) {
    asm volatile(
        "mma.sync.aligned.m16n8k16.row.col.f32.bf16.bf16.f32 "
        "{%0,%1,%2,%3}, {%4,%5,%6,%7}, {%8,%9}, {%0,%1,%2,%3};"
        : "+f"(c[0]), "+f"(c[1]), "+f"(c[2]), "+f"(c[3])
        : "r"(a[0]), "r"(a[1]), "r"(a[2]), "r"(a[3]), "r"(b[0]), "r"(b[1]));
}

template <int MODE>
__global__ __launch_bounds__(256, 1)
void gemm_mma(const float* __restrict__ A0, const float* __restrict__ A2,
              const float* __restrict__ Wl, const float* __restrict__ Wr,
              const float* __restrict__ bias, const float* __restrict__ rdeg,
              float* __restrict__ C) {
    __shared__ __align__(16) uint16_t AsH[128 * LDA], AsL[128 * LDA];
    __shared__ __align__(16) uint16_t BsH[128 * LDA], BsL[128 * LDA];

    const int tid  = threadIdx.x;
    const int wid  = tid >> 5;
    const int lane = tid & 31;
    const int g    = lane >> 2;      // group (row within 16-tile)
    const int tg   = lane & 3;
    const int row0 = blockIdx.x * 128;
    const int col0 = blockIdx.y * 128;
    const int wm   = wid >> 2;       // 0..1 -> 64-row slab
    const int wn   = wid & 3;        // 0..3 -> 32-col slab

    const uint32_t* AH32 = reinterpret_cast<const uint32_t*>(AsH);
    const uint32_t* AL32 = reinterpret_cast<const uint32_t*>(AsL);
    const uint32_t* BH32 = reinterpret_cast<const uint32_t*>(BsH);
    const uint32_t* BL32 = reinterpret_cast<const uint32_t*>(BsL);

    float acc[4][4][4];
#pragma unroll
    for (int i = 0; i < 4; i++)
#pragma unroll
        for (int j = 0; j < 4; j++)
#pragma unroll
            for (int k = 0; k < 4; k++) acc[i][j][k] = 0.f;

    for (int kt = 0; kt < 8; kt++) {
        const int k0 = kt * 32;

        // ---- load + split A tile: 128 rows x 32 cols (4 float4 per thread) ----
#pragma unroll
        for (int i = 0; i < 4; i++) {
            int g4  = tid * 4 + i;           // 0..1023
            int r   = g4 >> 3;               // 0..127
            int col = (g4 & 7) * 4;          // 0..28
            float4 v = make_float4(0.f, 0.f, 0.f, 0.f);
            int grow = row0 + r;
            if (grow < N_NODES) {
                if (MODE == 0) {
                    int k = k0 + col;
                    if (k < DIN) {
                        v = *reinterpret_cast<const float4*>(A0 + (size_t)grow * DIN + k);
                        float rd = rdeg[grow];
                        v.x *= rd; v.y *= rd; v.z *= rd; v.w *= rd;
                    } else {
                        v = *reinterpret_cast<const float4*>(A2 + (size_t)grow * DIN + (k - DIN));
                    }
                } else {
                    v = *reinterpret_cast<const float4*>(A0 + (size_t)grow * DHID + k0 + col);
                }
            }
            __nv_bfloat16 hx = __float2bfloat16_rn(v.x);
            __nv_bfloat16 hy = __float2bfloat16_rn(v.y);
            __nv_bfloat16 hz = __float2bfloat16_rn(v.z);
            __nv_bfloat16 hw = __float2bfloat16_rn(v.w);
            int idx32 = (r * LDA + col) >> 1;
            reinterpret_cast<uint32_t*>(AsH)[idx32]     = pack_bf16(v.x, v.y) ? pack_bf16(__bfloat162float(hx), __bfloat162float(hy)) * 0 + pack_bf16(__bfloat162float(hx), __bfloat162float(hy)) : 0; // placeholder removed below
        }
        // (the loop above is rewritten cleanly right after; see real loop)
        __syncthreads();
        break;
    }

    // ---- real implementation (the block above is dead after break; redo) ----
#pragma unroll
    for (int i = 0; i < 4; i++)
#pragma unroll
        for (int j = 0; j < 4; j++)
#pragma unroll
            for (int k = 0; k < 4; k++) acc[i][j][k] = 0.f;
    __syncthreads();

    for (int kt = 0; kt < 8; kt++) {
        const int k0 = kt * 32;

        // A tile
#pragma unroll
        for (int i = 0; i < 4; i++) {
            int g4  = tid * 4 + i;
            int r   = g4 >> 3;
            int col = (g4 & 7) * 4;
            float4 v = make_float4(0.f, 0.f, 0.f, 0.f);
            int grow = row0 + r;
            if (grow < N_NODES) {
                if (MODE == 0) {
                    int k = k0 + col;
                    if (k < DIN) {
                        v = *reinterpret_cast<const float4*>(A0 + (size_t)grow * DIN + k);
                        float rd = rdeg[grow];
                        v.x *= rd; v.y *= rd; v.z *= rd; v.w *= rd;
                    } else {
                        v = *reinterpret_cast<const float4*>(A2 + (size_t)grow * DIN + (k - DIN));
                    }
                } else {
                    v = *reinterpret_cast<const float4*>(A0 + (size_t)grow * DHID + k0 + col);
                }
            }
            float hx = __bfloat162float(__float2bfloat16_rn(v.x));
            float hy = __bfloat162float(__float2bfloat16_rn(v.y));
            float hz = __bfloat162float(__float2bfloat16_rn(v.z));
            float hw = __bfloat162float(__float2bfloat16_rn(v.w));
            int idx32 = (r * LDA + col) >> 1;
            reinterpret_cast<uint32_t*>(AsH)[idx32]     = pack_bf16(hx, hy);
            reinterpret_cast<uint32_t*>(AsH)[idx32 + 1] = pack_bf16(hz, hw);
            reinterpret_cast<uint32_t*>(AsL)[idx32]     = pack_bf16(v.x - hx, v.y - hy);
            reinterpret_cast<uint32_t*>(AsL)[idx32 + 1] = pack_bf16(v.z - hz, v.w - hw);
        }

        // B tile (rows = output cols col0..col0+127, k contiguous)
#pragma unroll
        for (int i = 0; i < 4; i++) {
            int g4  = tid * 4 + i;
            int r   = g4 >> 3;               // 0..127 (local col)
            int col = (g4 & 7) * 4;
            int j   = col0 + r;
            int k   = k0 + col;
            float4 v;
            if (MODE == 0) {
                v = (k < DIN)
                  ? *reinterpret_cast<const float4*>(Wl + (size_t)j * DIN + k)
                  : *reinterpret_cast<const float4*>(Wr + (size_t)j * DIN + (k - DIN));
            } else {
                v = (j < 128)
                  ? *reinterpret_cast<const float4*>(Wl + (size_t)j * DHID + k)
                  : *reinterpret_cast<const float4*>(Wr + (size_t)(j - 128) * DHID + k);
            }
            float hx = __bfloat162float(__float2bfloat16_rn(v.x));
            float hy = __bfloat162float(__float2bfloat16_rn(v.y));
            float hz = __bfloat162float(__float2bfloat16_rn(v.z));
            float hw = __bfloat162float(__float2bfloat16_rn(v.w));
            int idx32 = (r * LDA + col) >> 1;
            reinterpret_cast<uint32_t*>(BsH)[idx32]     = pack_bf16(hx, hy);
            reinterpret_cast<uint32_t*>(BsH)[idx32 + 1] = pack_bf16(hz, hw);
            reinterpret_cast<uint32_t*>(BsL)[idx32]     = pack_bf16(v.x - hx, v.y - hy);
            reinterpret_cast<uint32_t*>(BsL)[idx32 + 1] = pack_bf16(v.z - hz, v.w - hw);
        }
        __syncthreads();

        // ---- MMA over this 32-wide chunk: 2 x k16 ----
#pragma unroll
        for (int kk = 0; kk < 32; kk += 16) {
            uint32_t ah[4][4], al[4][4], bh[4][2], bl[4][2];
#pragma unroll
            for (int mt = 0; mt < 4; mt++) {
                int rbase = wm * 64 + mt * 16;
                int i00 = ((rbase + g) * LDA + kk) >> 1;      // row g,   k lo
                int i10 = ((rbase + g + 8) * LDA + kk) >> 1;  // row g+8, k lo
                ah[mt][0] = AH32[i00 + tg];
                ah[mt][1] = AH32[i10 + tg];
                ah[mt][2] = AH32[i00 + 4 + tg];
                ah[mt][3] = AH32[i10 + 4 + tg];
                al[mt][0] = AL32[i00 + tg];
                al[mt][1] = AL32[i10 + tg];
                al[mt][2] = AL32[i00 + 4 + tg];
                al[mt][3] = AL32[i10 + 4 + tg];
            }
#pragma unroll
            for (int nt = 0; nt < 4; nt++) {
                int cbase = wn * 32 + nt * 8;
                int i0 = ((cbase + g) * LDA + kk) >> 1;
                bh[nt][0] = BH32[i0 + tg];
                bh[nt][1] = BH32[i0 + 4 + tg];
                bl[nt][0] = BL32[i0 + tg];
                bl[nt][1] = BL32[i0 + 4 + tg];
            }
#pragma unroll
            for (int mt = 0; mt < 4; mt++)
#pragma unroll
                for (int nt = 0; nt < 4; nt++) {
                    mma_bf16(acc[mt][nt], ah[mt], bh[nt]);
                    mma_bf16(acc[mt][nt], ah[mt], bl[nt]);
                    mma_bf16(acc[mt][nt], al[mt], bh[nt]);
                }
        }
        __syncthreads();
    }

    // ---- epilogue ----
#pragma unroll
    for (int mt = 0; mt < 4; mt++) {
        int r0 = row0 + wm * 64 + mt * 16 + g;
#pragma unroll
        for (int half = 0; half < 2; half++) {
            int row = r0 + half * 8;
            if (row >= N_NODES) continue;
#pragma unroll
            for (int nt = 0; nt < 4; nt++) {
                int col = col0 + wn * 32 + nt * 8 + tg * 2;
                float c0 = acc[mt][nt][half * 2 + 0];
                float c1 = acc[mt][nt][half * 2 + 1];
                if (MODE == 0) {
                    c0 = fmaxf(c0 + __ldg(bias + col), 0.f);
                    c1 = fmaxf(c1 + __ldg(bias + col + 1), 0.f);
                }
                *reinterpret_cast<float2*>(C + (size_t)row * DHID + col) = make_float2(c0, c1);
            }
        }
    }
}

// ---------------------------------------------------------------------------
extern "C" void kernel_launch(void* const* d_in, const int* in_sizes, int n_in,
                              void* d_out, int out_size) {
    const float* x   = (const float*)d_in[0];
    const int*   ei  = (const int*)d_in[1];
    const float* W1l = (const float*)d_in[2];
    const float* b1  = (const float*)d_in[3];
    const float* W1r = (const float*)d_in[4];
    const float* W2l = (const float*)d_in[5];
    const float* b2  = (const float*)d_in[6];
    const float* W2r = (const float*)d_in[7];
    float* out = (float*)d_out;

    const int E = in_sizes[1] / 2;
    const int* src = ei;
    const int* dst = ei + E;

    float *deg, *agg, *h, *pq;
    cudaGetSymbolAddress((void**)&deg, g_deg);
    cudaGetSymbolAddress((void**)&agg, g_agg);
    cudaGetSymbolAddress((void**)&h,   g_h);
    cudaGetSymbolAddress((void**)&pq,  g_pq);

    const int AGG4 = N_NODES * DIN / 4;
    const dim3 GG((N_NODES + 127) / 128, 2);

    // degree + inverse
    zero_kernel<<<(N_NODES / 4 + 255) / 256, 256>>>((float4*)deg, N_NODES / 4);
    zero_kernel<<<(AGG4 + 255) / 256, 256>>>((float4*)agg, AGG4);
    deg_kernel<<<(E + 255) / 256, 256>>>(dst, E, deg);
    rdeg_kernel<<<(N_NODES + 255) / 256, 256>>>(deg);

    // layer 1
    scatter_kernel<<<(E + 7) / 8, 256>>>(x, DIN, src, dst, agg, E);
    gemm_mma<0><<<GG, 256>>>(agg, x, W1l, W1r, b1, deg, h);

    // layer 2
    gemm_mma<1><<<GG, 256>>>(h, nullptr, W2l, W2r, nullptr, nullptr, pq);
    zero_kernel<<<(AGG4 + 255) / 256, 256>>>((float4*)agg, AGG4);
    scatter_kernel<<<(E + 7) / 8, 256>>>(pq, DHID, src, dst, agg, E);
    final_kernel<<<(N_NODES * 32 + 255) / 256, 256>>>(agg, pq, deg, b2, out);
}

// round 4
// speedup vs baseline: 1.3796x; 1.1116x over previous
#include <cuda_runtime.h>
#include <cuda_bf16.h>
#include <cstdint>
#include <cstddef>

#define N_NODES 50000
#define DIN 128
#define DHID 256

// ---- scratch (static device globals; no allocation allowed) ----
__device__ float g_deg[N_NODES];
__device__ float g_agg[N_NODES * DIN];
__device__ float g_pq[N_NODES * DHID];
__device__ uint16_t g_a1h[N_NODES * DHID], g_a1l[N_NODES * DHID];   // layer1 A split
__device__ uint16_t g_hh[N_NODES * DHID],  g_hl[N_NODES * DHID];    // relu(h) split
__device__ uint16_t g_bh[2 * DHID * DHID], g_bl[2 * DHID * DHID];   // weight splits

// ---------------------------------------------------------------------------
__device__ __forceinline__ uint32_t smem_u32(const void* p) {
    uint32_t a;
    asm("{ .reg .u64 t; cvta.to.shared.u64 t, %1; cvt.u32.u64 %0, t; }" : "=r"(a) : "l"(p));
    return a;
}
__device__ __forceinline__ uint32_t pack_bf16(float x, float y) {
    __nv_bfloat162 t = __float22bfloat162_rn(make_float2(x, y));
    return *reinterpret_cast<uint32_t*>(&t);
}
// split v into hi (bf16-representable) + lo (residual), return packed pair words
__device__ __forceinline__ void split4(float4 v, uint32_t* hi2, uint32_t* lo2) {
    float hx = __bfloat162float(__float2bfloat16_rn(v.x));
    float hy = __bfloat162float(__float2bfloat16_rn(v.y));
    float hz = __bfloat162float(__float2bfloat16_rn(v.z));
    float hw = __bfloat162float(__float2bfloat16_rn(v.w));
    hi2[0] = pack_bf16(hx, hy);
    hi2[1] = pack_bf16(hz, hw);
    lo2[0] = pack_bf16(v.x - hx, v.y - hy);
    lo2[1] = pack_bf16(v.z - hz, v.w - hw);
}
__device__ __forceinline__ void cpa16(uint32_t saddr, const void* g, int sz) {
    asm volatile("cp.async.cg.shared.global [%0], [%1], 16, %2;" :: "r"(saddr), "l"(g), "r"(sz));
}
__device__ __forceinline__ void mma_bf16(float* c, const uint32_t* a, const uint32_t* b) {
    asm volatile(
        "mma.sync.aligned.m16n8k16.row.col.f32.bf16.bf16.f32 "
        "{%0,%1,%2,%3}, {%4,%5,%6,%7}, {%8,%9}, {%0,%1,%2,%3};"
        : "+f"(c[0]), "+f"(c[1]), "+f"(c[2]), "+f"(c[3])
        : "r"(a[0]), "r"(a[1]), "r"(a[2]), "r"(a[3]), "r"(b[0]), "r"(b[1]));
}

// ---------------------------------------------------------------------------
// small kernels
// ---------------------------------------------------------------------------
__global__ void zero_kernel(float4* __restrict__ p, int n4) {
    int i = blockIdx.x * blockDim.x + threadIdx.x;
    if (i < n4) p[i] = make_float4(0.f, 0.f, 0.f, 0.f);
}
__global__ void deg_kernel(const int* __restrict__ dst, int E, float* __restrict__ deg) {
    int i = blockIdx.x * blockDim.x + threadIdx.x;
    if (i < E) atomicAdd(&deg[dst[i]], 1.0f);
}
__global__ void rdeg_kernel(float* __restrict__ deg) {
    int i = blockIdx.x * blockDim.x + threadIdx.x;
    if (i < N_NODES) deg[i] = 1.0f / fmaxf(deg[i], 1.0f);
}

__global__ void scatter_kernel(const float* __restrict__ feat, int ld,
                               const int* __restrict__ src,
                               const int* __restrict__ dst,
                               float* __restrict__ agg, int E) {
    int e = blockIdx.x * (blockDim.x >> 5) + (threadIdx.x >> 5);
    if (e >= E) return;
    int lane = threadIdx.x & 31;
    int s = __ldg(src + e);
    int d = __ldg(dst + e);
    float4 v = __ldg(reinterpret_cast<const float4*>(feat + (size_t)s * ld) + lane);
    float* p = agg + (size_t)d * DIN + lane * 4;
    asm volatile("red.global.add.v4.f32 [%0], {%1,%2,%3,%4};"
                 :: "l"(p), "f"(v.x), "f"(v.y), "f"(v.z), "f"(v.w)
                 : "memory");
}

// build bf16 splits of both layers' B matrices:
// layer0: B(j,k) = k<128 ? W1l[j,k] : W1r[j,k-128]     (j,k in 0..255)
// layer1: B(j,k) = j<128 ? W2l[j,k] : W2r[j-128,k]
__global__ void split_w_kernel(const float* __restrict__ W1l, const float* __restrict__ W1r,
                               const float* __restrict__ W2l, const float* __restrict__ W2r,
                               uint16_t* __restrict__ bh, uint16_t* __restrict__ bl) {
    int t = blockIdx.x * blockDim.x + threadIdx.x;   // one per 4 elems; 2*65536/4
    if (t >= 2 * DHID * DHID / 4) return;
    int layer = t >> 14;
    int e0 = (t & 16383) * 4;
    int j = e0 >> 8, k = e0 & 255;
    float4 v;
    if (layer == 0) {
        v = (k < DIN) ? *reinterpret_cast<const float4*>(W1l + (size_t)j * DIN + k)
                      : *reinterpret_cast<const float4*>(W1r + (size_t)j * DIN + (k - DIN));
    } else {
        v = (j < 128) ? *reinterpret_cast<const float4*>(W2l + (size_t)j * DHID + k)
                      : *reinterpret_cast<const float4*>(W2r + (size_t)(j - 128) * DHID + k);
    }
    uint32_t hi2[2], lo2[2];
    split4(v, hi2, lo2);
    size_t o = (size_t)layer * DHID * DHID + e0;
    *reinterpret_cast<uint32_t*>(bh + o)     = hi2[0];
    *reinterpret_cast<uint32_t*>(bh + o + 2) = hi2[1];
    *reinterpret_cast<uint32_t*>(bl + o)     = lo2[0];
    *reinterpret_cast<uint32_t*>(bl + o + 2) = lo2[1];
}

// A1 = [agg*rdeg | x] -> bf16 split
__global__ void prep1_kernel(const float* __restrict__ agg, const float* __restrict__ x,
                             const float* __restrict__ rdeg,
                             uint16_t* __restrict__ ah, uint16_t* __restrict__ al) {
    int t = blockIdx.x * blockDim.x + threadIdx.x;   // one per 4 elems
    if (t >= N_NODES * DHID / 4) return;
    int row = t >> 6;
    int c = (t & 63) * 4;
    float4 v;
    if (c < DIN) {
        v = *reinterpret_cast<const float4*>(agg + (size_t)row * DIN + c);
        float rd = rdeg[row];
        v.x *= rd; v.y *= rd; v.z *= rd; v.w *= rd;
    } else {
        v = *reinterpret_cast<const float4*>(x + (size_t)row * DIN + (c - DIN));
    }
    uint32_t hi2[2], lo2[2];
    split4(v, hi2, lo2);
    size_t o = (size_t)row * DHID + c;
    *reinterpret_cast<uint32_t*>(ah + o)     = hi2[0];
    *reinterpret_cast<uint32_t*>(ah + o + 2) = hi2[1];
    *reinterpret_cast<uint32_t*>(al + o)     = lo2[0];
    *reinterpret_cast<uint32_t*>(al + o + 2) = lo2[1];
}

__global__ void final_kernel(const float* __restrict__ agg,
                             const float* __restrict__ pq,
                             const float* __restrict__ rdeg,
                             const float* __restrict__ b2,
                             float* __restrict__ out) {
    int t = blockIdx.x * blockDim.x + threadIdx.x;
    if (t >= N_NODES * 32) return;
    int row = t >> 5;
    int q = (t & 31) * 4;
    float rd = rdeg[row];
    float4 a  = *reinterpret_cast<const float4*>(agg + (size_t)row * DIN + q);
    float4 qv = *reinterpret_cast<const float4*>(pq + (size_t)row * DHID + 128 + q);
    float4 bb = *reinterpret_cast<const float4*>(b2 + q);
    float4 o;
    o.x = a.x * rd + qv.x + bb.x;
    o.y = a.y * rd + qv.y + bb.y;
    o.z = a.z * rd + qv.z + bb.z;
    o.w = a.w * rd + qv.w + bb.w;
    *reinterpret_cast<float4*>(out + (size_t)row * DIN + q) = o;
}

// ---------------------------------------------------------------------------
// Pure bf16-split tensor-core GEMM: all operands pre-split in gmem.
// C[M,256] = A[M,256] @ B[256,256]^T, 3 MMA terms.
// Block 128x128 (grid.y=2), 8 warps (64x32 each), k-chunk 32, cp.async double buffer.
// MODE 0: epilogue relu(+bias) -> write bf16 split (Ch, Cl)
// MODE 1: epilogue plain       -> write fp32 C
// ---------------------------------------------------------------------------
#define LDA 40                       // bf16 elems per smem row (80B, 16B-aligned)
#define ST_ELEMS (128 * LDA)         // 5120 elems per array per stage
#define ST_U32   (ST_ELEMS / 2)      // 2560

template <int MODE>
__global__ __launch_bounds__(256, 1)
void gemm_mma(const uint16_t* __restrict__ Ah, const uint16_t* __restrict__ Al,
              const uint16_t* __restrict__ Bh, const uint16_t* __restrict__ Bl,
              const float* __restrict__ bias,
              float* __restrict__ C, uint16_t* __restrict__ Ch, uint16_t* __restrict__ Cl) {
    extern __shared__ __align__(16) uint16_t smem[];
    const uint32_t sb = smem_u32(smem);
    uint32_t* sm32 = reinterpret_cast<uint32_t*>(smem);

    const int tid  = threadIdx.x;
    const int wid  = tid >> 5;
    const int lane = tid & 31;
    const int g    = lane >> 2;
    const int tg   = lane & 3;
    const int row0 = blockIdx.x * 128;
    const int col0 = blockIdx.y * 128;
    const int wm   = wid >> 2;
    const int wn   = wid & 3;

    // per-thread load map: for each of 4 arrays, 2 chunks of 16B
    const int q0  = tid * 2;
    const int lr0 = q0 >> 2, ls0 = (q0 & 3) * 8;        // row, elem-offset of chunk 0
    const int lr1 = (q0 + 1) >> 2, ls1 = ((q0 + 1) & 3) * 8;

    float acc[4][4][4];
#pragma unroll
    for (int i = 0; i < 4; i++)
#pragma unroll
        for (int j = 0; j < 4; j++)
#pragma unroll
            for (int k = 0; k < 4; k++) acc[i][j][k] = 0.f;

    auto load_stage = [&](int kt, int s) {
        const int k0 = kt * 32;
        const uint32_t sbase = sb + (uint32_t)(s * 4 * ST_ELEMS) * 2;
        // A rows (zero-fill OOB via src-size 0)
        {
            int r0a = row0 + lr0, r1a = row0 + lr1;
            int sz0 = (r0a < N_NODES) ? 16 : 0;
            int sz1 = (r1a < N_NODES) ? 16 : 0;
            size_t o0 = (size_t)min(r0a, N_NODES - 1) * DHID + k0 + ls0;
            size_t o1 = (size_t)min(r1a, N_NODES - 1) * DHID + k0 + ls1;
            cpa16(sbase + (lr0 * LDA + ls0) * 2, Ah + o0, sz0);
            cpa16(sbase + (lr1 * LDA + ls1) * 2, Ah + o1, sz1);
            cpa16(sbase + (ST_ELEMS + lr0 * LDA + ls0) * 2, Al + o0, sz0);
            cpa16(sbase + (ST_ELEMS + lr1 * LDA + ls1) * 2, Al + o1, sz1);
        }
        // B rows (always in range)
        {
            size_t o0 = (size_t)(col0 + lr0) * DHID + k0 + ls0;
            size_t o1 = (size_t)(col0 + lr1) * DHID + k0 + ls1;
            cpa16(sbase + (2 * ST_ELEMS + lr0 * LDA + ls0) * 2, Bh + o0, 16);
            cpa16(sbase + (2 * ST_ELEMS + lr1 * LDA + ls1) * 2, Bh + o1, 16);
            cpa16(sbase + (3 * ST_ELEMS + lr0 * LDA + ls0) * 2, Bl + o0, 16);
            cpa16(sbase + (3 * ST_ELEMS + lr1 * LDA + ls1) * 2, Bl + o1, 16);
        }
        asm volatile("cp.async.commit_group;");
    };

    load_stage(0, 0);

    for (int kt = 0; kt < 8; kt++) {
        const int s = kt & 1;
        if (kt < 7) load_stage(kt + 1, s ^ 1);
        if (kt < 7) asm volatile("cp.async.wait_group 1;");
        else        asm volatile("cp.async.wait_group 0;");
        __syncthreads();

        const uint32_t* AH32 = sm32 + s * 4 * ST_U32;
        const uint32_t* AL32 = AH32 + ST_U32;
        const uint32_t* BH32 = AH32 + 2 * ST_U32;
        const uint32_t* BL32 = AH32 + 3 * ST_U32;

#pragma unroll
        for (int kk = 0; kk < 32; kk += 16) {
            uint32_t ah[4][4], al[4][4], bh[4][2], bl[4][2];
#pragma unroll
            for (int mt = 0; mt < 4; mt++) {
                int rbase = wm * 64 + mt * 16;
                int i00 = ((rbase + g) * LDA + kk) >> 1;
                int i10 = ((rbase + g + 8) * LDA + kk) >> 1;
                ah[mt][0] = AH32[i00 + tg];
                ah[mt][1] = AH32[i10 + tg];
                ah[mt][2] = AH32[i00 + 4 + tg];
                ah[mt][3] = AH32[i10 + 4 + tg];
                al[mt][0] = AL32[i00 + tg];
                al[mt][1] = AL32[i10 + tg];
                al[mt][2] = AL32[i00 + 4 + tg];
                al[mt][3] = AL32[i10 + 4 + tg];
            }
#pragma unroll
            for (int nt = 0; nt < 4; nt++) {
                int cbase = wn * 32 + nt * 8;
                int i0 = ((cbase + g) * LDA + kk) >> 1;
                bh[nt][0] = BH32[i0 + tg];
                bh[nt][1] = BH32[i0 + 4 + tg];
                bl[nt][0] = BL32[i0 + tg];
                bl[nt][1] = BL32[i0 + 4 + tg];
            }
#pragma unroll
            for (int mt = 0; mt < 4; mt++)
#pragma unroll
                for (int nt = 0; nt < 4; nt++) {
                    mma_bf16(acc[mt][nt], ah[mt], bh[nt]);
                    mma_bf16(acc[mt][nt], ah[mt], bl[nt]);
                    mma_bf16(acc[mt][nt], al[mt], bh[nt]);
                }
        }
        __syncthreads();
    }

    // ---- epilogue ----
#pragma unroll
    for (int mt = 0; mt < 4; mt++) {
        int r0 = row0 + wm * 64 + mt * 16 + g;
#pragma unroll
        for (int half = 0; half < 2; half++) {
            int row = r0 + half * 8;
            if (row >= N_NODES) continue;
#pragma unroll
            for (int nt = 0; nt < 4; nt++) {
                int col = col0 + wn * 32 + nt * 8 + tg * 2;
                float c0 = acc[mt][nt][half * 2 + 0];
                float c1 = acc[mt][nt][half * 2 + 1];
                if (MODE == 0) {
                    c0 = fmaxf(c0 + __ldg(bias + col), 0.f);
                    c1 = fmaxf(c1 + __ldg(bias + col + 1), 0.f);
                    float h0 = __bfloat162float(__float2bfloat16_rn(c0));
                    float h1 = __bfloat162float(__float2bfloat16_rn(c1));
                    size_t o = (size_t)row * DHID + col;
                    *reinterpret_cast<uint32_t*>(Ch + o) = pack_bf16(h0, h1);
                    *reinterpret_cast<uint32_t*>(Cl + o) = pack_bf16(c0 - h0, c1 - h1);
                } else {
                    *reinterpret_cast<float2*>(C + (size_t)row * DHID + col) = make_float2(c0, c1);
                }
            }
        }
    }
}

// ---------------------------------------------------------------------------
extern "C" void kernel_launch(void* const* d_in, const int* in_sizes, int n_in,
                              void* d_out, int out_size) {
    const float* x   = (const float*)d_in[0];
    const int*   ei  = (const int*)d_in[1];
    const float* W1l = (const float*)d_in[2];
    const float* b1  = (const float*)d_in[3];
    const float* W1r = (const float*)d_in[4];
    const float* W2l = (const float*)d_in[5];
    const float* b2  = (const float*)d_in[6];
    const float* W2r = (const float*)d_in[7];
    float* out = (float*)d_out;

    const int E = in_sizes[1] / 2;
    const int* src = ei;
    const int* dst = ei + E;

    float *deg, *agg, *pq;
    uint16_t *a1h, *a1l, *hh, *hl, *bh, *bl;
    cudaGetSymbolAddress((void**)&deg, g_deg);
    cudaGetSymbolAddress((void**)&agg, g_agg);
    cudaGetSymbolAddress((void**)&pq,  g_pq);
    cudaGetSymbolAddress((void**)&a1h, g_a1h);
    cudaGetSymbolAddress((void**)&a1l, g_a1l);
    cudaGetSymbolAddress((void**)&hh,  g_hh);
    cudaGetSymbolAddress((void**)&hl,  g_hl);
    cudaGetSymbolAddress((void**)&bh,  g_bh);
    cudaGetSymbolAddress((void**)&bl,  g_bl);

    const int SMEM = 2 * 4 * ST_ELEMS * 2;   // 2 stages * 4 arrays * 5120 elems * 2B = 81920
    static bool attr_done = false;
    if (!attr_done) {
        cudaFuncSetAttribute(gemm_mma<0>, cudaFuncAttributeMaxDynamicSharedMemorySize, SMEM);
        cudaFuncSetAttribute(gemm_mma<1>, cudaFuncAttributeMaxDynamicSharedMemorySize, SMEM);
        attr_done = true;
    }

    const int AGG4 = N_NODES * DIN / 4;
    const dim3 GG((N_NODES + 127) / 128, 2);

    // degree + inverse + weight split (independent of edges/scatter results)
    zero_kernel<<<(N_NODES / 4 + 255) / 256, 256>>>((float4*)deg, N_NODES / 4);
    zero_kernel<<<(AGG4 + 255) / 256, 256>>>((float4*)agg, AGG4);
    deg_kernel<<<(E + 255) / 256, 256>>>(dst, E, deg);
    rdeg_kernel<<<(N_NODES + 255) / 256, 256>>>(deg);
    split_w_kernel<<<(2 * DHID * DHID / 4 + 255) / 256, 256>>>(W1l, W1r, W2l, W2r, bh, bl);

    // layer 1
    scatter_kernel<<<(E + 7) / 8, 256>>>(x, DIN, src, dst, agg, E);
    prep1_kernel<<<(N_NODES * DHID / 4 + 255) / 256, 256>>>(agg, x, deg, a1h, a1l);
    gemm_mma<0><<<GG, 256, SMEM>>>(a1h, a1l, bh, bl, b1, nullptr, hh, hl);

    // layer 2
    gemm_mma<1><<<GG, 256, SMEM>>>(hh, hl, bh + DHID * DHID, bl + DHID * DHID,
                                   nullptr, pq, nullptr, nullptr);
    zero_kernel<<<(AGG4 + 255) / 256, 256>>>((float4*)agg, AGG4);
    scatter_kernel<<<(E + 7) / 8, 256>>>(pq, DHID, src, dst, agg, E);
    final_kernel<<<(N_NODES * 32 + 255) / 256, 256>>>(agg, pq, deg, b2, out);
}

// round 5
// speedup vs baseline: 1.6055x; 1.1637x over previous
#include <cuda_runtime.h>
#include <cuda_bf16.h>
#include <cstdint>
#include <cstddef>

#define N_NODES 50000
#define DIN 128
#define DHID 256
#define E_MAX 1000000

// ---- scratch (static device globals; no allocation allowed) ----
__device__ int g_degi[N_NODES];
__device__ int g_off[N_NODES + 1];
__device__ int g_cur[N_NODES];
__device__ int g_esrc[E_MAX];
__device__ float g_pq[N_NODES * DHID];
__device__ uint16_t g_a1h[N_NODES * DHID], g_a1l[N_NODES * DHID];   // layer1 A split
__device__ uint16_t g_hh[N_NODES * DHID],  g_hl[N_NODES * DHID];    // relu(h) split
__device__ uint16_t g_bh[2 * DHID * DHID], g_bl[2 * DHID * DHID];   // weight splits

// ---------------------------------------------------------------------------
__device__ __forceinline__ uint32_t smem_u32(const void* p) {
    uint32_t a;
    asm("{ .reg .u64 t; cvta.to.shared.u64 t, %1; cvt.u32.u64 %0, t; }" : "=r"(a) : "l"(p));
    return a;
}
__device__ __forceinline__ uint32_t pack_bf16(float x, float y) {
    __nv_bfloat162 t = __float22bfloat162_rn(make_float2(x, y));
    return *reinterpret_cast<uint32_t*>(&t);
}
__device__ __forceinline__ void split4(float4 v, uint32_t* hi2, uint32_t* lo2) {
    float hx = __bfloat162float(__float2bfloat16_rn(v.x));
    float hy = __bfloat162float(__float2bfloat16_rn(v.y));
    float hz = __bfloat162float(__float2bfloat16_rn(v.z));
    float hw = __bfloat162float(__float2bfloat16_rn(v.w));
    hi2[0] = pack_bf16(hx, hy);
    hi2[1] = pack_bf16(hz, hw);
    lo2[0] = pack_bf16(v.x - hx, v.y - hy);
    lo2[1] = pack_bf16(v.z - hz, v.w - hw);
}
__device__ __forceinline__ void cpa16(uint32_t saddr, const void* g, int sz) {
    asm volatile("cp.async.cg.shared.global [%0], [%1], 16, %2;" :: "r"(saddr), "l"(g), "r"(sz));
}
__device__ __forceinline__ void mma_bf16(float* c, const uint32_t* a, const uint32_t* b) {
    asm volatile(
        "mma.sync.aligned.m16n8k16.row.col.f32.bf16.bf16.f32 "
        "{%0,%1,%2,%3}, {%4,%5,%6,%7}, {%8,%9}, {%0,%1,%2,%3};"
        : "+f"(c[0]), "+f"(c[1]), "+f"(c[2]), "+f"(c[3])
        : "r"(a[0]), "r"(a[1]), "r"(a[2]), "r"(a[3]), "r"(b[0]), "r"(b[1]));
}

// ---------------------------------------------------------------------------
// CSR build
// ---------------------------------------------------------------------------
__global__ void zero_int_kernel(int* __restrict__ p, int n) {
    int i = blockIdx.x * blockDim.x + threadIdx.x;
    if (i < n) p[i] = 0;
}
__global__ void degi_kernel(const int* __restrict__ dst, int E, int* __restrict__ degi) {
    int i = blockIdx.x * blockDim.x + threadIdx.x;
    if (i < E) atomicAdd(&degi[dst[i]], 1);
}
// single block, 1024 threads: exclusive prefix of degi -> off; zero cur
__global__ __launch_bounds__(1024)
void prefix_kernel(const int* __restrict__ degi, int* __restrict__ off,
                   int* __restrict__ cur, int E) {
    __shared__ int part[1024];
    const int t = threadIdx.x;
    const int CH = (N_NODES + 1023) / 1024;
    const int base = t * CH;
    int s = 0;
#pragma unroll 4
    for (int i = 0; i < CH; i++) {
        int idx = base + i;
        if (idx < N_NODES) s += degi[idx];
    }
    part[t] = s;
    __syncthreads();
    for (int o = 1; o < 1024; o <<= 1) {
        int v = (t >= o) ? part[t - o] : 0;
        __syncthreads();
        part[t] += v;
        __syncthreads();
    }
    int run = (t == 0) ? 0 : part[t - 1];
#pragma unroll 4
    for (int i = 0; i < CH; i++) {
        int idx = base + i;
        if (idx < N_NODES) {
            off[idx] = run;
            run += degi[idx];
            cur[idx] = 0;
        }
    }
    if (t == 0) off[N_NODES] = E;
}
__global__ void fill_kernel(const int* __restrict__ src, const int* __restrict__ dst,
                            const int* __restrict__ off, int* __restrict__ cur,
                            int* __restrict__ esrc, int E) {
    int e = blockIdx.x * blockDim.x + threadIdx.x;
    if (e >= E) return;
    int d = dst[e];
    int p = atomicAdd(&cur[d], 1);
    esrc[off[d] + p] = src[e];
}

// ---------------------------------------------------------------------------
// weight split (layer0: K-concat of W1l|W1r ; layer1: N-concat of W2l;W2r)
// ---------------------------------------------------------------------------
__global__ void split_w_kernel(const float* __restrict__ W1l, const float* __restrict__ W1r,
                               const float* __restrict__ W2l, const float* __restrict__ W2r,
                               uint16_t* __restrict__ bh, uint16_t* __restrict__ bl) {
    int t = blockIdx.x * blockDim.x + threadIdx.x;
    if (t >= 2 * DHID * DHID / 4) return;
    int layer = t >> 14;
    int e0 = (t & 16383) * 4;
    int j = e0 >> 8, k = e0 & 255;
    float4 v;
    if (layer == 0) {
        v = (k < DIN) ? *reinterpret_cast<const float4*>(W1l + (size_t)j * DIN + k)
                      : *reinterpret_cast<const float4*>(W1r + (size_t)j * DIN + (k - DIN));
    } else {
        v = (j < 128) ? *reinterpret_cast<const float4*>(W2l + (size_t)j * DHID + k)
                      : *reinterpret_cast<const float4*>(W2r + (size_t)(j - 128) * DHID + k);
    }
    uint32_t hi2[2], lo2[2];
    split4(v, hi2, lo2);
    size_t o = (size_t)layer * DHID * DHID + e0;
    *reinterpret_cast<uint32_t*>(bh + o)     = hi2[0];
    *reinterpret_cast<uint32_t*>(bh + o + 2) = hi2[1];
    *reinterpret_cast<uint32_t*>(bl + o)     = lo2[0];
    *reinterpret_cast<uint32_t*>(bl + o + 2) = lo2[1];
}

// ---------------------------------------------------------------------------
// CSR aggregation, one warp per node, 4-edge unroll.
// MODE 0: feat = x (ld 128). epilogue: A1 = [mean | x] -> bf16 split (ah, al)
// MODE 1: feat = pq cols 0..127 (ld 256). epilogue: out = mean + b2 + q (fp32)
// ---------------------------------------------------------------------------
template <int MODE>
__global__ __launch_bounds__(256)
void agg_csr_kernel(const float* __restrict__ feat,
                    const int* __restrict__ off, const int* __restrict__ esrc,
                    uint16_t* __restrict__ ah, uint16_t* __restrict__ al,
                    const float* __restrict__ b2, float* __restrict__ out) {
    const int d = blockIdx.x * 8 + (threadIdx.x >> 5);
    if (d >= N_NODES) return;
    const int lane = threadIdx.x & 31;
    const int LD4 = (MODE == 0) ? (DIN / 4) : (DHID / 4);
    const float4* F = reinterpret_cast<const float4*>(feat);

    const int beg = __ldg(off + d);
    const int end = __ldg(off + d + 1);

    float4 a0 = make_float4(0.f, 0.f, 0.f, 0.f), a1 = a0, a2 = a0, a3 = a0;
    int i = beg;
    for (; i + 4 <= end; i += 4) {
        int s0 = __ldg(esrc + i), s1 = __ldg(esrc + i + 1);
        int s2 = __ldg(esrc + i + 2), s3 = __ldg(esrc + i + 3);
        float4 v0 = __ldg(F + (size_t)s0 * LD4 + lane);
        float4 v1 = __ldg(F + (size_t)s1 * LD4 + lane);
        float4 v2 = __ldg(F + (size_t)s2 * LD4 + lane);
        float4 v3 = __ldg(F + (size_t)s3 * LD4 + lane);
        a0.x += v0.x; a0.y += v0.y; a0.z += v0.z; a0.w += v0.w;
        a1.x += v1.x; a1.y += v1.y; a1.z += v1.z; a1.w += v1.w;
        a2.x += v2.x; a2.y += v2.y; a2.z += v2.z; a2.w += v2.w;
        a3.x += v3.x; a3.y += v3.y; a3.z += v3.z; a3.w += v3.w;
    }
    for (; i < end; i++) {
        int s = __ldg(esrc + i);
        float4 v = __ldg(F + (size_t)s * LD4 + lane);
        a0.x += v.x; a0.y += v.y; a0.z += v.z; a0.w += v.w;
    }
    float4 acc;
    acc.x = (a0.x + a1.x) + (a2.x + a3.x);
    acc.y = (a0.y + a1.y) + (a2.y + a3.y);
    acc.z = (a0.z + a1.z) + (a2.z + a3.z);
    acc.w = (a0.w + a1.w) + (a2.w + a3.w);

    const float rd = 1.0f / (float)max(end - beg, 1);
    acc.x *= rd; acc.y *= rd; acc.z *= rd; acc.w *= rd;

    if (MODE == 0) {
        uint32_t hi2[2], lo2[2];
        size_t o = (size_t)d * DHID + lane * 4;
        split4(acc, hi2, lo2);
        *reinterpret_cast<uint32_t*>(ah + o)     = hi2[0];
        *reinterpret_cast<uint32_t*>(ah + o + 2) = hi2[1];
        *reinterpret_cast<uint32_t*>(al + o)     = lo2[0];
        *reinterpret_cast<uint32_t*>(al + o + 2) = lo2[1];
        // x half -> cols 128..255
        float4 xv = __ldg(F + (size_t)d * LD4 + lane);
        split4(xv, hi2, lo2);
        o += DIN;
        *reinterpret_cast<uint32_t*>(ah + o)     = hi2[0];
        *reinterpret_cast<uint32_t*>(ah + o + 2) = hi2[1];
        *reinterpret_cast<uint32_t*>(al + o)     = lo2[0];
        *reinterpret_cast<uint32_t*>(al + o + 2) = lo2[1];
    } else {
        float4 qv = __ldg(F + (size_t)d * LD4 + (DIN / 4) + lane);
        float4 bb = __ldg(reinterpret_cast<const float4*>(b2) + lane);
        float4 o;
        o.x = acc.x + qv.x + bb.x;
        o.y = acc.y + qv.y + bb.y;
        o.z = acc.z + qv.z + bb.z;
        o.w = acc.w + qv.w + bb.w;
        reinterpret_cast<float4*>(out)[(size_t)d * (DIN / 4) + lane] = o;
    }
}

// ---------------------------------------------------------------------------
// bf16-split tensor-core GEMM (unchanged from R4; proven)
// ---------------------------------------------------------------------------
#define LDA 40
#define ST_ELEMS (128 * LDA)
#define ST_U32   (ST_ELEMS / 2)

template <int MODE>
__global__ __launch_bounds__(256, 1)
void gemm_mma(const uint16_t* __restrict__ Ah, const uint16_t* __restrict__ Al,
              const uint16_t* __restrict__ Bh, const uint16_t* __restrict__ Bl,
              const float* __restrict__ bias,
              float* __restrict__ C, uint16_t* __restrict__ Ch, uint16_t* __restrict__ Cl) {
    extern __shared__ __align__(16) uint16_t smem[];
    const uint32_t sb = smem_u32(smem);
    uint32_t* sm32 = reinterpret_cast<uint32_t*>(smem);

    const int tid  = threadIdx.x;
    const int wid  = tid >> 5;
    const int lane = tid & 31;
    const int g    = lane >> 2;
    const int tg   = lane & 3;
    const int row0 = blockIdx.x * 128;
    const int col0 = blockIdx.y * 128;
    const int wm   = wid >> 2;
    const int wn   = wid & 3;

    const int q0  = tid * 2;
    const int lr0 = q0 >> 2, ls0 = (q0 & 3) * 8;
    const int lr1 = (q0 + 1) >> 2, ls1 = ((q0 + 1) & 3) * 8;

    float acc[4][4][4];
#pragma unroll
    for (int i = 0; i < 4; i++)
#pragma unroll
        for (int j = 0; j < 4; j++)
#pragma unroll
            for (int k = 0; k < 4; k++) acc[i][j][k] = 0.f;

    auto load_stage = [&](int kt, int s) {
        const int k0 = kt * 32;
        const uint32_t sbase = sb + (uint32_t)(s * 4 * ST_ELEMS) * 2;
        {
            int r0a = row0 + lr0, r1a = row0 + lr1;
            int sz0 = (r0a < N_NODES) ? 16 : 0;
            int sz1 = (r1a < N_NODES) ? 16 : 0;
            size_t o0 = (size_t)min(r0a, N_NODES - 1) * DHID + k0 + ls0;
            size_t o1 = (size_t)min(r1a, N_NODES - 1) * DHID + k0 + ls1;
            cpa16(sbase + (lr0 * LDA + ls0) * 2, Ah + o0, sz0);
            cpa16(sbase + (lr1 * LDA + ls1) * 2, Ah + o1, sz1);
            cpa16(sbase + (ST_ELEMS + lr0 * LDA + ls0) * 2, Al + o0, sz0);
            cpa16(sbase + (ST_ELEMS + lr1 * LDA + ls1) * 2, Al + o1, sz1);
        }
        {
            size_t o0 = (size_t)(col0 + lr0) * DHID + k0 + ls0;
            size_t o1 = (size_t)(col0 + lr1) * DHID + k0 + ls1;
            cpa16(sbase + (2 * ST_ELEMS + lr0 * LDA + ls0) * 2, Bh + o0, 16);
            cpa16(sbase + (2 * ST_ELEMS + lr1 * LDA + ls1) * 2, Bh + o1, 16);
            cpa16(sbase + (3 * ST_ELEMS + lr0 * LDA + ls0) * 2, Bl + o0, 16);
            cpa16(sbase + (3 * ST_ELEMS + lr1 * LDA + ls1) * 2, Bl + o1, 16);
        }
        asm volatile("cp.async.commit_group;");
    };

    load_stage(0, 0);

    for (int kt = 0; kt < 8; kt++) {
        const int s = kt & 1;
        if (kt < 7) load_stage(kt + 1, s ^ 1);
        if (kt < 7) asm volatile("cp.async.wait_group 1;");
        else        asm volatile("cp.async.wait_group 0;");
        __syncthreads();

        const uint32_t* AH32 = sm32 + s * 4 * ST_U32;
        const uint32_t* AL32 = AH32 + ST_U32;
        const uint32_t* BH32 = AH32 + 2 * ST_U32;
        const uint32_t* BL32 = AH32 + 3 * ST_U32;

#pragma unroll
        for (int kk = 0; kk < 32; kk += 16) {
            uint32_t ah[4][4], al[4][4], bh[4][2], bl[4][2];
#pragma unroll
            for (int mt = 0; mt < 4; mt++) {
                int rbase = wm * 64 + mt * 16;
                int i00 = ((rbase + g) * LDA + kk) >> 1;
                int i10 = ((rbase + g + 8) * LDA + kk) >> 1;
                ah[mt][0] = AH32[i00 + tg];
                ah[mt][1] = AH32[i10 + tg];
                ah[mt][2] = AH32[i00 + 4 + tg];
                ah[mt][3] = AH32[i10 + 4 + tg];
                al[mt][0] = AL32[i00 + tg];
                al[mt][1] = AL32[i10 + tg];
                al[mt][2] = AL32[i00 + 4 + tg];
                al[mt][3] = AL32[i10 + 4 + tg];
            }
#pragma unroll
            for (int nt = 0; nt < 4; nt++) {
                int cbase = wn * 32 + nt * 8;
                int i0 = ((cbase + g) * LDA + kk) >> 1;
                bh[nt][0] = BH32[i0 + tg];
                bh[nt][1] = BH32[i0 + 4 + tg];
                bl[nt][0] = BL32[i0 + tg];
                bl[nt][1] = BL32[i0 + 4 + tg];
            }
#pragma unroll
            for (int mt = 0; mt < 4; mt++)
#pragma unroll
                for (int nt = 0; nt < 4; nt++) {
                    mma_bf16(acc[mt][nt], ah[mt], bh[nt]);
                    mma_bf16(acc[mt][nt], ah[mt], bl[nt]);
                    mma_bf16(acc[mt][nt], al[mt], bh[nt]);
                }
        }
        __syncthreads();
    }

#pragma unroll
    for (int mt = 0; mt < 4; mt++) {
        int r0 = row0 + wm * 64 + mt * 16 + g;
#pragma unroll
        for (int half = 0; half < 2; half++) {
            int row = r0 + half * 8;
            if (row >= N_NODES) continue;
#pragma unroll
            for (int nt = 0; nt < 4; nt++) {
                int col = col0 + wn * 32 + nt * 8 + tg * 2;
                float c0 = acc[mt][nt][half * 2 + 0];
                float c1 = acc[mt][nt][half * 2 + 1];
                if (MODE == 0) {
                    c0 = fmaxf(c0 + __ldg(bias + col), 0.f);
                    c1 = fmaxf(c1 + __ldg(bias + col + 1), 0.f);
                    float h0 = __bfloat162float(__float2bfloat16_rn(c0));
                    float h1 = __bfloat162float(__float2bfloat16_rn(c1));
                    size_t o = (size_t)row * DHID + col;
                    *reinterpret_cast<uint32_t*>(Ch + o) = pack_bf16(h0, h1);
                    *reinterpret_cast<uint32_t*>(Cl + o) = pack_bf16(c0 - h0, c1 - h1);
                } else {
                    *reinterpret_cast<float2*>(C + (size_t)row * DHID + col) = make_float2(c0, c1);
                }
            }
        }
    }
}

// ---------------------------------------------------------------------------
extern "C" void kernel_launch(void* const* d_in, const int* in_sizes, int n_in,
                              void* d_out, int out_size) {
    const float* x   = (const float*)d_in[0];
    const int*   ei  = (const int*)d_in[1];
    const float* W1l = (const float*)d_in[2];
    const float* b1  = (const float*)d_in[3];
    const float* W1r = (const float*)d_in[4];
    const float* W2l = (const float*)d_in[5];
    const float* b2  = (const float*)d_in[6];
    const float* W2r = (const float*)d_in[7];
    float* out = (float*)d_out;

    const int E = in_sizes[1] / 2;
    const int* src = ei;
    const int* dst = ei + E;

    int *degi, *off, *cur, *esrc;
    float *pq;
    uint16_t *a1h, *a1l, *hh, *hl, *bh, *bl;
    cudaGetSymbolAddress((void**)&degi, g_degi);
    cudaGetSymbolAddress((void**)&off,  g_off);
    cudaGetSymbolAddress((void**)&cur,  g_cur);
    cudaGetSymbolAddress((void**)&esrc, g_esrc);
    cudaGetSymbolAddress((void**)&pq,   g_pq);
    cudaGetSymbolAddress((void**)&a1h,  g_a1h);
    cudaGetSymbolAddress((void**)&a1l,  g_a1l);
    cudaGetSymbolAddress((void**)&hh,   g_hh);
    cudaGetSymbolAddress((void**)&hl,   g_hl);
    cudaGetSymbolAddress((void**)&bh,   g_bh);
    cudaGetSymbolAddress((void**)&bl,   g_bl);

    const int SMEM = 2 * 4 * ST_ELEMS * 2;   // 81920 B
    static bool attr_done = false;
    if (!attr_done) {
        cudaFuncSetAttribute(gemm_mma<0>, cudaFuncAttributeMaxDynamicSharedMemorySize, SMEM);
        cudaFuncSetAttribute(gemm_mma<1>, cudaFuncAttributeMaxDynamicSharedMemorySize, SMEM);
        attr_done = true;
    }

    const dim3 GG((N_NODES + 127) / 128, 2);
    const int AGG_GRID = (N_NODES + 7) / 8;

    // CSR build
    zero_int_kernel<<<(N_NODES + 255) / 256, 256>>>(degi, N_NODES);
    degi_kernel<<<(E + 255) / 256, 256>>>(dst, E, degi);
    prefix_kernel<<<1, 1024>>>(degi, off, cur, E);
    fill_kernel<<<(E + 255) / 256, 256>>>(src, dst, off, cur, esrc, E);
    split_w_kernel<<<(2 * DHID * DHID / 4 + 255) / 256, 256>>>(W1l, W1r, W2l, W2r, bh, bl);

    // layer 1: agg+prep fused -> GEMM (writes relu(h) as bf16 split)
    agg_csr_kernel<0><<<AGG_GRID, 256>>>(x, off, esrc, a1h, a1l, nullptr, nullptr);
    gemm_mma<0><<<GG, 256, SMEM>>>(a1h, a1l, bh, bl, b1, nullptr, hh, hl);

    // layer 2: GEMM -> agg+final fused (writes out directly)
    gemm_mma<1><<<GG, 256, SMEM>>>(hh, hl, bh + DHID * DHID, bl + DHID * DHID,
                                   nullptr, pq, nullptr, nullptr);
    agg_csr_kernel<1><<<AGG_GRID, 256>>>(pq, off, esrc, nullptr, nullptr, b2, out);
}

// round 6
// speedup vs baseline: 1.6527x; 1.0294x over previous
#include <cuda_runtime.h>
#include <cuda_bf16.h>
#include <cstdint>
#include <cstddef>

#define N_NODES 50000
#define DIN 128
#define DHID 256
#define E_MAX 1000000

// ---- scratch (static device globals; no allocation allowed) ----
__device__ int g_degi[N_NODES];
__device__ int g_off[N_NODES + 1];
__device__ int g_cur[N_NODES];
__device__ int g_esrc[E_MAX];
__device__ float g_pq[N_NODES * DHID];
__device__ uint16_t g_a1h[N_NODES * DHID], g_a1l[N_NODES * DHID];   // layer1 A split
__device__ uint16_t g_hh[N_NODES * DHID],  g_hl[N_NODES * DHID];    // relu(h) split
__device__ uint16_t g_bh[2 * DHID * DHID], g_bl[2 * DHID * DHID];   // weight splits

// ---------------------------------------------------------------------------
__device__ __forceinline__ uint32_t smem_u32(const void* p) {
    uint32_t a;
    asm("{ .reg .u64 t; cvta.to.shared.u64 t, %1; cvt.u32.u64 %0, t; }" : "=r"(a) : "l"(p));
    return a;
}
__device__ __forceinline__ uint32_t pack_bf16(float x, float y) {
    __nv_bfloat162 t = __float22bfloat162_rn(make_float2(x, y));
    return *reinterpret_cast<uint32_t*>(&t);
}
__device__ __forceinline__ void split4(float4 v, uint32_t* hi2, uint32_t* lo2) {
    float hx = __bfloat162float(__float2bfloat16_rn(v.x));
    float hy = __bfloat162float(__float2bfloat16_rn(v.y));
    float hz = __bfloat162float(__float2bfloat16_rn(v.z));
    float hw = __bfloat162float(__float2bfloat16_rn(v.w));
    hi2[0] = pack_bf16(hx, hy);
    hi2[1] = pack_bf16(hz, hw);
    lo2[0] = pack_bf16(v.x - hx, v.y - hy);
    lo2[1] = pack_bf16(v.z - hz, v.w - hw);
}
__device__ __forceinline__ void cpa16(uint32_t saddr, const void* g, int sz) {
    asm volatile("cp.async.cg.shared.global [%0], [%1], 16, %2;" :: "r"(saddr), "l"(g), "r"(sz));
}
__device__ __forceinline__ void mma_bf16(float* c, const uint32_t* a, const uint32_t* b) {
    asm volatile(
        "mma.sync.aligned.m16n8k16.row.col.f32.bf16.bf16.f32 "
        "{%0,%1,%2,%3}, {%4,%5,%6,%7}, {%8,%9}, {%0,%1,%2,%3};"
        : "+f"(c[0]), "+f"(c[1]), "+f"(c[2]), "+f"(c[3])
        : "r"(a[0]), "r"(a[1]), "r"(a[2]), "r"(a[3]), "r"(b[0]), "r"(b[1]));
}
__device__ __forceinline__ void ldsm4(uint32_t* r, uint32_t a) {
    asm volatile("ldmatrix.sync.aligned.m8n8.x4.shared.b16 {%0,%1,%2,%3}, [%4];"
                 : "=r"(r[0]), "=r"(r[1]), "=r"(r[2]), "=r"(r[3]) : "r"(a));
}

// ---------------------------------------------------------------------------
// CSR build
// ---------------------------------------------------------------------------
__global__ void zero_int_kernel(int* __restrict__ p, int n) {
    int i = blockIdx.x * blockDim.x + threadIdx.x;
    if (i < n) p[i] = 0;
}
__global__ void degi_kernel(const int* __restrict__ dst, int E, int* __restrict__ degi) {
    int i = blockIdx.x * blockDim.x + threadIdx.x;
    if (i < E) atomicAdd(&degi[dst[i]], 1);
}
__global__ __launch_bounds__(1024)
void prefix_kernel(const int* __restrict__ degi, int* __restrict__ off,
                   int* __restrict__ cur, int E) {
    __shared__ int part[1024];
    const int t = threadIdx.x;
    const int CH = (N_NODES + 1023) / 1024;
    const int base = t * CH;
    int s = 0;
#pragma unroll 4
    for (int i = 0; i < CH; i++) {
        int idx = base + i;
        if (idx < N_NODES) s += degi[idx];
    }
    part[t] = s;
    __syncthreads();
    for (int o = 1; o < 1024; o <<= 1) {
        int v = (t >= o) ? part[t - o] : 0;
        __syncthreads();
        part[t] += v;
        __syncthreads();
    }
    int run = (t == 0) ? 0 : part[t - 1];
#pragma unroll 4
    for (int i = 0; i < CH; i++) {
        int idx = base + i;
        if (idx < N_NODES) {
            off[idx] = run;
            run += degi[idx];
            cur[idx] = 0;
        }
    }
    if (t == 0) off[N_NODES] = E;
}
__global__ void fill_kernel(const int* __restrict__ src, const int* __restrict__ dst,
                            const int* __restrict__ off, int* __restrict__ cur,
                            int* __restrict__ esrc, int E) {
    int e = blockIdx.x * blockDim.x + threadIdx.x;
    if (e >= E) return;
    int d = dst[e];
    int p = atomicAdd(&cur[d], 1);
    esrc[off[d] + p] = src[e];
}

// ---------------------------------------------------------------------------
// weight split
// ---------------------------------------------------------------------------
__global__ void split_w_kernel(const float* __restrict__ W1l, const float* __restrict__ W1r,
                               const float* __restrict__ W2l, const float* __restrict__ W2r,
                               uint16_t* __restrict__ bh, uint16_t* __restrict__ bl) {
    int t = blockIdx.x * blockDim.x + threadIdx.x;
    if (t >= 2 * DHID * DHID / 4) return;
    int layer = t >> 14;
    int e0 = (t & 16383) * 4;
    int j = e0 >> 8, k = e0 & 255;
    float4 v;
    if (layer == 0) {
        v = (k < DIN) ? *reinterpret_cast<const float4*>(W1l + (size_t)j * DIN + k)
                      : *reinterpret_cast<const float4*>(W1r + (size_t)j * DIN + (k - DIN));
    } else {
        v = (j < 128) ? *reinterpret_cast<const float4*>(W2l + (size_t)j * DHID + k)
                      : *reinterpret_cast<const float4*>(W2r + (size_t)(j - 128) * DHID + k);
    }
    uint32_t hi2[2], lo2[2];
    split4(v, hi2, lo2);
    size_t o = (size_t)layer * DHID * DHID + e0;
    *reinterpret_cast<uint32_t*>(bh + o)     = hi2[0];
    *reinterpret_cast<uint32_t*>(bh + o + 2) = hi2[1];
    *reinterpret_cast<uint32_t*>(bl + o)     = lo2[0];
    *reinterpret_cast<uint32_t*>(bl + o + 2) = lo2[1];
}

// ---------------------------------------------------------------------------
// CSR aggregation (unchanged; near LTS-read floor)
// ---------------------------------------------------------------------------
template <int MODE>
__global__ __launch_bounds__(256)
void agg_csr_kernel(const float* __restrict__ feat,
                    const int* __restrict__ off, const int* __restrict__ esrc,
                    uint16_t* __restrict__ ah, uint16_t* __restrict__ al,
                    const float* __restrict__ b2, float* __restrict__ out) {
    const int d = blockIdx.x * 8 + (threadIdx.x >> 5);
    if (d >= N_NODES) return;
    const int lane = threadIdx.x & 31;
    const int LD4 = (MODE == 0) ? (DIN / 4) : (DHID / 4);
    const float4* F = reinterpret_cast<const float4*>(feat);

    const int beg = __ldg(off + d);
    const int end = __ldg(off + d + 1);

    float4 a0 = make_float4(0.f, 0.f, 0.f, 0.f), a1 = a0, a2 = a0, a3 = a0;
    int i = beg;
    for (; i + 4 <= end; i += 4) {
        int s0 = __ldg(esrc + i), s1 = __ldg(esrc + i + 1);
        int s2 = __ldg(esrc + i + 2), s3 = __ldg(esrc + i + 3);
        float4 v0 = __ldg(F + (size_t)s0 * LD4 + lane);
        float4 v1 = __ldg(F + (size_t)s1 * LD4 + lane);
        float4 v2 = __ldg(F + (size_t)s2 * LD4 + lane);
        float4 v3 = __ldg(F + (size_t)s3 * LD4 + lane);
        a0.x += v0.x; a0.y += v0.y; a0.z += v0.z; a0.w += v0.w;
        a1.x += v1.x; a1.y += v1.y; a1.z += v1.z; a1.w += v1.w;
        a2.x += v2.x; a2.y += v2.y; a2.z += v2.z; a2.w += v2.w;
        a3.x += v3.x; a3.y += v3.y; a3.z += v3.z; a3.w += v3.w;
    }
    for (; i < end; i++) {
        int s = __ldg(esrc + i);
        float4 v = __ldg(F + (size_t)s * LD4 + lane);
        a0.x += v.x; a0.y += v.y; a0.z += v.z; a0.w += v.w;
    }
    float4 acc;
    acc.x = (a0.x + a1.x) + (a2.x + a3.x);
    acc.y = (a0.y + a1.y) + (a2.y + a3.y);
    acc.z = (a0.z + a1.z) + (a2.z + a3.z);
    acc.w = (a0.w + a1.w) + (a2.w + a3.w);

    const float rd = 1.0f / (float)max(end - beg, 1);
    acc.x *= rd; acc.y *= rd; acc.z *= rd; acc.w *= rd;

    if (MODE == 0) {
        uint32_t hi2[2], lo2[2];
        size_t o = (size_t)d * DHID + lane * 4;
        split4(acc, hi2, lo2);
        *reinterpret_cast<uint32_t*>(ah + o)     = hi2[0];
        *reinterpret_cast<uint32_t*>(ah + o + 2) = hi2[1];
        *reinterpret_cast<uint32_t*>(al + o)     = lo2[0];
        *reinterpret_cast<uint32_t*>(al + o + 2) = lo2[1];
        float4 xv = __ldg(F + (size_t)d * LD4 + lane);
        split4(xv, hi2, lo2);
        o += DIN;
        *reinterpret_cast<uint32_t*>(ah + o)     = hi2[0];
        *reinterpret_cast<uint32_t*>(ah + o + 2) = hi2[1];
        *reinterpret_cast<uint32_t*>(al + o)     = lo2[0];
        *reinterpret_cast<uint32_t*>(al + o + 2) = lo2[1];
    } else {
        float4 qv = __ldg(F + (size_t)d * LD4 + (DIN / 4) + lane);
        float4 bb = __ldg(reinterpret_cast<const float4*>(b2) + lane);
        float4 o;
        o.x = acc.x + qv.x + bb.x;
        o.y = acc.y + qv.y + bb.y;
        o.z = acc.z + qv.z + bb.z;
        o.w = acc.w + qv.w + bb.w;
        reinterpret_cast<float4*>(out)[(size_t)d * (DIN / 4) + lane] = o;
    }
}

// ---------------------------------------------------------------------------
// bf16-split tensor-core GEMM with ldmatrix fragment loads
// ---------------------------------------------------------------------------
#define LDA 40
#define ST_ELEMS (128 * LDA)

template <int MODE>
__global__ __launch_bounds__(256, 1)
void gemm_mma(const uint16_t* __restrict__ Ah, const uint16_t* __restrict__ Al,
              const uint16_t* __restrict__ Bh, const uint16_t* __restrict__ Bl,
              const float* __restrict__ bias,
              float* __restrict__ C, uint16_t* __restrict__ Ch, uint16_t* __restrict__ Cl) {
    extern __shared__ __align__(16) uint16_t smem[];
    const uint32_t sb = smem_u32(smem);

    const int tid  = threadIdx.x;
    const int wid  = tid >> 5;
    const int lane = tid & 31;
    const int g    = lane >> 2;
    const int tg   = lane & 3;
    const int row0 = blockIdx.x * 128;
    const int col0 = blockIdx.y * 128;
    const int wm   = wid >> 2;
    const int wn   = wid & 3;

    // cp.async load map
    const int q0  = tid * 2;
    const int lr0 = q0 >> 2, ls0 = (q0 & 3) * 8;
    const int lr1 = (q0 + 1) >> 2, ls1 = ((q0 + 1) & 3) * 8;

    // ldmatrix per-lane address terms (elems)
    const int aTerm = (lane & 15) * LDA + (lane >> 4) * 8;
    const int bTerm = ((lane & 7) + ((lane >> 4) << 3)) * LDA + ((lane >> 3) & 1) * 8;
    const int aTileOff = (wm * 64) * LDA;   // + mt*16*LDA + kk
    const int bTileOff = (wn * 32) * LDA;   // + p*16*LDA + kk

    float acc[4][4][4];
#pragma unroll
    for (int i = 0; i < 4; i++)
#pragma unroll
        for (int j = 0; j < 4; j++)
#pragma unroll
            for (int k = 0; k < 4; k++) acc[i][j][k] = 0.f;

    auto load_stage = [&](int kt, int s) {
        const int k0 = kt * 32;
        const uint32_t sbase = sb + (uint32_t)(s * 4 * ST_ELEMS) * 2;
        {
            int r0a = row0 + lr0, r1a = row0 + lr1;
            int sz0 = (r0a < N_NODES) ? 16 : 0;
            int sz1 = (r1a < N_NODES) ? 16 : 0;
            size_t o0 = (size_t)min(r0a, N_NODES - 1) * DHID + k0 + ls0;
            size_t o1 = (size_t)min(r1a, N_NODES - 1) * DHID + k0 + ls1;
            cpa16(sbase + (lr0 * LDA + ls0) * 2, Ah + o0, sz0);
            cpa16(sbase + (lr1 * LDA + ls1) * 2, Ah + o1, sz1);
            cpa16(sbase + (ST_ELEMS + lr0 * LDA + ls0) * 2, Al + o0, sz0);
            cpa16(sbase + (ST_ELEMS + lr1 * LDA + ls1) * 2, Al + o1, sz1);
        }
        {
            size_t o0 = (size_t)(col0 + lr0) * DHID + k0 + ls0;
            size_t o1 = (size_t)(col0 + lr1) * DHID + k0 + ls1;
            cpa16(sbase + (2 * ST_ELEMS + lr0 * LDA + ls0) * 2, Bh + o0, 16);
            cpa16(sbase + (2 * ST_ELEMS + lr1 * LDA + ls1) * 2, Bh + o1, 16);
            cpa16(sbase + (3 * ST_ELEMS + lr0 * LDA + ls0) * 2, Bl + o0, 16);
            cpa16(sbase + (3 * ST_ELEMS + lr1 * LDA + ls1) * 2, Bl + o1, 16);
        }
        asm volatile("cp.async.commit_group;");
    };

    load_stage(0, 0);

    for (int kt = 0; kt < 8; kt++) {
        const int s = kt & 1;
        if (kt < 7) load_stage(kt + 1, s ^ 1);
        if (kt < 7) asm volatile("cp.async.wait_group 1;");
        else        asm volatile("cp.async.wait_group 0;");
        __syncthreads();

        const uint32_t stg = sb + (uint32_t)(s * 4 * ST_ELEMS) * 2;
        const uint32_t aBaseH = stg + (uint32_t)(aTerm + aTileOff) * 2;
        const uint32_t aBaseL = aBaseH + (uint32_t)ST_ELEMS * 2;
        const uint32_t bBaseH = stg + (uint32_t)(2 * ST_ELEMS + bTerm + bTileOff) * 2;
        const uint32_t bBaseL = bBaseH + (uint32_t)ST_ELEMS * 2;

#pragma unroll
        for (int kk = 0; kk < 32; kk += 16) {
            uint32_t ah[4][4], al[4][4], bh[4][2], bl[4][2];
#pragma unroll
            for (int mt = 0; mt < 4; mt++) {
                uint32_t off = (uint32_t)(mt * 16 * LDA + kk) * 2;
                ldsm4(ah[mt], aBaseH + off);
                ldsm4(al[mt], aBaseL + off);
            }
#pragma unroll
            for (int p = 0; p < 2; p++) {
                uint32_t off = (uint32_t)(p * 16 * LDA + kk) * 2;
                uint32_t t[4];
                ldsm4(t, bBaseH + off);
                bh[2 * p][0] = t[0]; bh[2 * p][1] = t[1];
                bh[2 * p + 1][0] = t[2]; bh[2 * p + 1][1] = t[3];
                ldsm4(t, bBaseL + off);
                bl[2 * p][0] = t[0]; bl[2 * p][1] = t[1];
                bl[2 * p + 1][0] = t[2]; bl[2 * p + 1][1] = t[3];
            }
#pragma unroll
            for (int mt = 0; mt < 4; mt++)
#pragma unroll
                for (int nt = 0; nt < 4; nt++) {
                    mma_bf16(acc[mt][nt], ah[mt], bh[nt]);
                    mma_bf16(acc[mt][nt], ah[mt], bl[nt]);
                    mma_bf16(acc[mt][nt], al[mt], bh[nt]);
                }
        }
        __syncthreads();
    }

#pragma unroll
    for (int mt = 0; mt < 4; mt++) {
        int r0 = row0 + wm * 64 + mt * 16 + g;
#pragma unroll
        for (int half = 0; half < 2; half++) {
            int row = r0 + half * 8;
            if (row >= N_NODES) continue;
#pragma unroll
            for (int nt = 0; nt < 4; nt++) {
                int col = col0 + wn * 32 + nt * 8 + tg * 2;
                float c0 = acc[mt][nt][half * 2 + 0];
                float c1 = acc[mt][nt][half * 2 + 1];
                if (MODE == 0) {
                    c0 = fmaxf(c0 + __ldg(bias + col), 0.f);
                    c1 = fmaxf(c1 + __ldg(bias + col + 1), 0.f);
                    float h0 = __bfloat162float(__float2bfloat16_rn(c0));
                    float h1 = __bfloat162float(__float2bfloat16_rn(c1));
                    size_t o = (size_t)row * DHID + col;
                    *reinterpret_cast<uint32_t*>(Ch + o) = pack_bf16(h0, h1);
                    *reinterpret_cast<uint32_t*>(Cl + o) = pack_bf16(c0 - h0, c1 - h1);
                } else {
                    *reinterpret_cast<float2*>(C + (size_t)row * DHID + col) = make_float2(c0, c1);
                }
            }
        }
    }
}

// ---------------------------------------------------------------------------
extern "C" void kernel_launch(void* const* d_in, const int* in_sizes, int n_in,
                              void* d_out, int out_size) {
    const float* x   = (const float*)d_in[0];
    const int*   ei  = (const int*)d_in[1];
    const float* W1l = (const float*)d_in[2];
    const float* b1  = (const float*)d_in[3];
    const float* W1r = (const float*)d_in[4];
    const float* W2l = (const float*)d_in[5];
    const float* b2  = (const float*)d_in[6];
    const float* W2r = (const float*)d_in[7];
    float* out = (float*)d_out;

    const int E = in_sizes[1] / 2;
    const int* src = ei;
    const int* dst = ei + E;

    int *degi, *off, *cur, *esrc;
    float *pq;
    uint16_t *a1h, *a1l, *hh, *hl, *bh, *bl;
    cudaGetSymbolAddress((void**)&degi, g_degi);
    cudaGetSymbolAddress((void**)&off,  g_off);
    cudaGetSymbolAddress((void**)&cur,  g_cur);
    cudaGetSymbolAddress((void**)&esrc, g_esrc);
    cudaGetSymbolAddress((void**)&pq,   g_pq);
    cudaGetSymbolAddress((void**)&a1h,  g_a1h);
    cudaGetSymbolAddress((void**)&a1l,  g_a1l);
    cudaGetSymbolAddress((void**)&hh,   g_hh);
    cudaGetSymbolAddress((void**)&hl,   g_hl);
    cudaGetSymbolAddress((void**)&bh,   g_bh);
    cudaGetSymbolAddress((void**)&bl,   g_bl);

    const int SMEM = 2 * 4 * ST_ELEMS * 2;   // 81920 B
    static bool attr_done = false;
    if (!attr_done) {
        cudaFuncSetAttribute(gemm_mma<0>, cudaFuncAttributeMaxDynamicSharedMemorySize, SMEM);
        cudaFuncSetAttribute(gemm_mma<1>, cudaFuncAttributeMaxDynamicSharedMemorySize, SMEM);
        attr_done = true;
    }

    const dim3 GG((N_NODES + 127) / 128, 2);
    const int AGG_GRID = (N_NODES + 7) / 8;

    // CSR build
    zero_int_kernel<<<(N_NODES + 255) / 256, 256>>>(degi, N_NODES);
    degi_kernel<<<(E + 255) / 256, 256>>>(dst, E, degi);
    prefix_kernel<<<1, 1024>>>(degi, off, cur, E);
    fill_kernel<<<(E + 255) / 256, 256>>>(src, dst, off, cur, esrc, E);
    split_w_kernel<<<(2 * DHID * DHID / 4 + 255) / 256, 256>>>(W1l, W1r, W2l, W2r, bh, bl);

    // layer 1
    agg_csr_kernel<0><<<AGG_GRID, 256>>>(x, off, esrc, a1h, a1l, nullptr, nullptr);
    gemm_mma<0><<<GG, 256, SMEM>>>(a1h, a1l, bh, bl, b1, nullptr, hh, hl);

    // layer 2
    gemm_mma<1><<<GG, 256, SMEM>>>(hh, hl, bh + DHID * DHID, bl + DHID * DHID,
                                   nullptr, pq, nullptr, nullptr);
    agg_csr_kernel<1><<<AGG_GRID, 256>>>(pq, off, esrc, nullptr, nullptr, b2, out);
}

// round 7
// speedup vs baseline: 1.7484x; 1.0579x over previous
#include <cuda_runtime.h>
#include <cuda_bf16.h>
#include <cstdint>
#include <cstddef>

#define N_NODES 50000
#define DIN 128
#define DHID 256
#define E_MAX 1000000

// ---- scratch (static device globals; no allocation allowed) ----
__device__ int g_degi[N_NODES];
__device__ int g_off[N_NODES + 1];
__device__ int g_cur[N_NODES];
__device__ int g_esrc[E_MAX];
__device__ float g_pq[N_NODES * DHID];
__device__ uint16_t g_a1h[N_NODES * DHID], g_a1l[N_NODES * DHID];   // layer1 A split
__device__ uint16_t g_hh[N_NODES * DHID],  g_hl[N_NODES * DHID];    // relu(h) split
__device__ uint16_t g_bh[2 * DHID * DHID], g_bl[2 * DHID * DHID];   // weight splits

// ---------------------------------------------------------------------------
__device__ __forceinline__ uint32_t smem_u32(const void* p) {
    uint32_t a;
    asm("{ .reg .u64 t; cvta.to.shared.u64 t, %1; cvt.u32.u64 %0, t; }" : "=r"(a) : "l"(p));
    return a;
}
__device__ __forceinline__ uint32_t pack_bf16(float x, float y) {
    __nv_bfloat162 t = __float22bfloat162_rn(make_float2(x, y));
    return *reinterpret_cast<uint32_t*>(&t);
}
__device__ __forceinline__ void split4(float4 v, uint32_t* hi2, uint32_t* lo2) {
    float hx = __bfloat162float(__float2bfloat16_rn(v.x));
    float hy = __bfloat162float(__float2bfloat16_rn(v.y));
    float hz = __bfloat162float(__float2bfloat16_rn(v.z));
    float hw = __bfloat162float(__float2bfloat16_rn(v.w));
    hi2[0] = pack_bf16(hx, hy);
    hi2[1] = pack_bf16(hz, hw);
    lo2[0] = pack_bf16(v.x - hx, v.y - hy);
    lo2[1] = pack_bf16(v.z - hz, v.w - hw);
}
__device__ __forceinline__ void cpa16(uint32_t saddr, const void* g, int sz) {
    asm volatile("cp.async.cg.shared.global [%0], [%1], 16, %2;" :: "r"(saddr), "l"(g), "r"(sz));
}
__device__ __forceinline__ void mma_bf16(float* c, const uint32_t* a, const uint32_t* b) {
    asm volatile(
        "mma.sync.aligned.m16n8k16.row.col.f32.bf16.bf16.f32 "
        "{%0,%1,%2,%3}, {%4,%5,%6,%7}, {%8,%9}, {%0,%1,%2,%3};"
        : "+f"(c[0]), "+f"(c[1]), "+f"(c[2]), "+f"(c[3])
        : "r"(a[0]), "r"(a[1]), "r"(a[2]), "r"(a[3]), "r"(b[0]), "r"(b[1]));
}
__device__ __forceinline__ void ldsm4(uint32_t* r, uint32_t a) {
    asm volatile("ldmatrix.sync.aligned.m8n8.x4.shared.b16 {%0,%1,%2,%3}, [%4];"
                 : "=r"(r[0]), "=r"(r[1]), "=r"(r[2]), "=r"(r[3]) : "r"(a));
}

// ---------------------------------------------------------------------------
// CSR build
// ---------------------------------------------------------------------------
__global__ void zero_int_kernel(int* __restrict__ p, int n) {
    int i = blockIdx.x * blockDim.x + threadIdx.x;
    if (i < n) p[i] = 0;
}
__global__ void degi_kernel(const int* __restrict__ dst, int E, int* __restrict__ degi) {
    int i = blockIdx.x * blockDim.x + threadIdx.x;
    if (i < E) atomicAdd(&degi[dst[i]], 1);
}
__global__ __launch_bounds__(1024)
void prefix_kernel(const int* __restrict__ degi, int* __restrict__ off,
                   int* __restrict__ cur, int E) {
    __shared__ int part[1024];
    const int t = threadIdx.x;
    const int CH = (N_NODES + 1023) / 1024;
    const int base = t * CH;
    int s = 0;
#pragma unroll 4
    for (int i = 0; i < CH; i++) {
        int idx = base + i;
        if (idx < N_NODES) s += degi[idx];
    }
    part[t] = s;
    __syncthreads();
    for (int o = 1; o < 1024; o <<= 1) {
        int v = (t >= o) ? part[t - o] : 0;
        __syncthreads();
        part[t] += v;
        __syncthreads();
    }
    int run = (t == 0) ? 0 : part[t - 1];
#pragma unroll 4
    for (int i = 0; i < CH; i++) {
        int idx = base + i;
        if (idx < N_NODES) {
            off[idx] = run;
            run += degi[idx];
            cur[idx] = 0;
        }
    }
    if (t == 0) off[N_NODES] = E;
}
__global__ void fill_kernel(const int* __restrict__ src, const int* __restrict__ dst,
                            const int* __restrict__ off, int* __restrict__ cur,
                            int* __restrict__ esrc, int E) {
    int e = blockIdx.x * blockDim.x + threadIdx.x;
    if (e >= E) return;
    int d = dst[e];
    int p = atomicAdd(&cur[d], 1);
    esrc[off[d] + p] = src[e];
}

// ---------------------------------------------------------------------------
// weight split
// ---------------------------------------------------------------------------
__global__ void split_w_kernel(const float* __restrict__ W1l, const float* __restrict__ W1r,
                               const float* __restrict__ W2l, const float* __restrict__ W2r,
                               uint16_t* __restrict__ bh, uint16_t* __restrict__ bl) {
    int t = blockIdx.x * blockDim.x + threadIdx.x;
    if (t >= 2 * DHID * DHID / 4) return;
    int layer = t >> 14;
    int e0 = (t & 16383) * 4;
    int j = e0 >> 8, k = e0 & 255;
    float4 v;
    if (layer == 0) {
        v = (k < DIN) ? *reinterpret_cast<const float4*>(W1l + (size_t)j * DIN + k)
                      : *reinterpret_cast<const float4*>(W1r + (size_t)j * DIN + (k - DIN));
    } else {
        v = (j < 128) ? *reinterpret_cast<const float4*>(W2l + (size_t)j * DHID + k)
                      : *reinterpret_cast<const float4*>(W2r + (size_t)(j - 128) * DHID + k);
    }
    uint32_t hi2[2], lo2[2];
    split4(v, hi2, lo2);
    size_t o = (size_t)layer * DHID * DHID + e0;
    *reinterpret_cast<uint32_t*>(bh + o)     = hi2[0];
    *reinterpret_cast<uint32_t*>(bh + o + 2) = hi2[1];
    *reinterpret_cast<uint32_t*>(bl + o)     = lo2[0];
    *reinterpret_cast<uint32_t*>(bl + o + 2) = lo2[1];
}

// ---------------------------------------------------------------------------
// CSR aggregation (near LTS-read floor)
// ---------------------------------------------------------------------------
template <int MODE>
__global__ __launch_bounds__(256)
void agg_csr_kernel(const float* __restrict__ feat,
                    const int* __restrict__ off, const int* __restrict__ esrc,
                    uint16_t* __restrict__ ah, uint16_t* __restrict__ al,
                    const float* __restrict__ b2, float* __restrict__ out) {
    const int d = blockIdx.x * 8 + (threadIdx.x >> 5);
    if (d >= N_NODES) return;
    const int lane = threadIdx.x & 31;
    const int LD4 = (MODE == 0) ? (DIN / 4) : (DHID / 4);
    const float4* F = reinterpret_cast<const float4*>(feat);

    const int beg = __ldg(off + d);
    const int end = __ldg(off + d + 1);

    float4 a0 = make_float4(0.f, 0.f, 0.f, 0.f), a1 = a0, a2 = a0, a3 = a0;
    int i = beg;
    for (; i + 4 <= end; i += 4) {
        int s0 = __ldg(esrc + i), s1 = __ldg(esrc + i + 1);
        int s2 = __ldg(esrc + i + 2), s3 = __ldg(esrc + i + 3);
        float4 v0 = __ldg(F + (size_t)s0 * LD4 + lane);
        float4 v1 = __ldg(F + (size_t)s1 * LD4 + lane);
        float4 v2 = __ldg(F + (size_t)s2 * LD4 + lane);
        float4 v3 = __ldg(F + (size_t)s3 * LD4 + lane);
        a0.x += v0.x; a0.y += v0.y; a0.z += v0.z; a0.w += v0.w;
        a1.x += v1.x; a1.y += v1.y; a1.z += v1.z; a1.w += v1.w;
        a2.x += v2.x; a2.y += v2.y; a2.z += v2.z; a2.w += v2.w;
        a3.x += v3.x; a3.y += v3.y; a3.z += v3.z; a3.w += v3.w;
    }
    for (; i < end; i++) {
        int s = __ldg(esrc + i);
        float4 v = __ldg(F + (size_t)s * LD4 + lane);
        a0.x += v.x; a0.y += v.y; a0.z += v.z; a0.w += v.w;
    }
    float4 acc;
    acc.x = (a0.x + a1.x) + (a2.x + a3.x);
    acc.y = (a0.y + a1.y) + (a2.y + a3.y);
    acc.z = (a0.z + a1.z) + (a2.z + a3.z);
    acc.w = (a0.w + a1.w) + (a2.w + a3.w);

    const float rd = 1.0f / (float)max(end - beg, 1);
    acc.x *= rd; acc.y *= rd; acc.z *= rd; acc.w *= rd;

    if (MODE == 0) {
        uint32_t hi2[2], lo2[2];
        size_t o = (size_t)d * DHID + lane * 4;
        split4(acc, hi2, lo2);
        *reinterpret_cast<uint32_t*>(ah + o)     = hi2[0];
        *reinterpret_cast<uint32_t*>(ah + o + 2) = hi2[1];
        *reinterpret_cast<uint32_t*>(al + o)     = lo2[0];
        *reinterpret_cast<uint32_t*>(al + o + 2) = lo2[1];
        float4 xv = __ldg(F + (size_t)d * LD4 + lane);
        split4(xv, hi2, lo2);
        o += DIN;
        *reinterpret_cast<uint32_t*>(ah + o)     = hi2[0];
        *reinterpret_cast<uint32_t*>(ah + o + 2) = hi2[1];
        *reinterpret_cast<uint32_t*>(al + o)     = lo2[0];
        *reinterpret_cast<uint32_t*>(al + o + 2) = lo2[1];
    } else {
        float4 qv = __ldg(F + (size_t)d * LD4 + (DIN / 4) + lane);
        float4 bb = __ldg(reinterpret_cast<const float4*>(b2) + lane);
        float4 o;
        o.x = acc.x + qv.x + bb.x;
        o.y = acc.y + qv.y + bb.y;
        o.z = acc.z + qv.z + bb.z;
        o.w = acc.w + qv.w + bb.w;
        reinterpret_cast<float4*>(out)[(size_t)d * (DIN / 4) + lane] = o;
    }
}

// ---------------------------------------------------------------------------
// bf16-split tensor-core GEMM: 256x128 tile, 512 threads (16 warps, 4/SMSP)
// ---------------------------------------------------------------------------
#define LDA 40
#define ST_A (256 * LDA)             // 10240 elems per A array per stage
#define ST_B (128 * LDA)             // 5120 elems per B array per stage
#define ST_TOTAL (2 * ST_A + 2 * ST_B)   // 30720 elems per stage
#define OFF_AL ST_A
#define OFF_BH (2 * ST_A)
#define OFF_BL (2 * ST_A + ST_B)

template <int MODE>
__global__ __launch_bounds__(512, 1)
void gemm_mma(const uint16_t* __restrict__ Ah, const uint16_t* __restrict__ Al,
              const uint16_t* __restrict__ Bh, const uint16_t* __restrict__ Bl,
              const float* __restrict__ bias,
              float* __restrict__ C, uint16_t* __restrict__ Ch, uint16_t* __restrict__ Cl) {
    extern __shared__ __align__(16) uint16_t smem[];
    const uint32_t sb = smem_u32(smem);

    const int tid  = threadIdx.x;
    const int wid  = tid >> 5;
    const int lane = tid & 31;
    const int g    = lane >> 2;
    const int tg   = lane & 3;
    const int row0 = blockIdx.x * 256;
    const int col0 = blockIdx.y * 128;
    const int wm   = wid >> 2;       // 0..3 -> 64-row slab
    const int wn   = wid & 3;        // 0..3 -> 32-col slab

    // cp.async load map: A chunks q = tid*2, tid*2+1 (0..1023); B chunk q = tid (0..511)
    const int qa0 = tid * 2;
    const int ar0 = qa0 >> 2, as0 = (qa0 & 3) * 8;
    const int ar1 = (qa0 + 1) >> 2, as1 = ((qa0 + 1) & 3) * 8;
    const int br = tid >> 2, bs = (tid & 3) * 8;

    // ldmatrix per-lane address terms (elems)
    const int aTerm = (lane & 15) * LDA + (lane >> 4) * 8;
    const int bTerm = ((lane & 7) + ((lane >> 4) << 3)) * LDA + ((lane >> 3) & 1) * 8;
    const int aTileOff = (wm * 64) * LDA;
    const int bTileOff = (wn * 32) * LDA;

    float acc[4][4][4];
#pragma unroll
    for (int i = 0; i < 4; i++)
#pragma unroll
        for (int j = 0; j < 4; j++)
#pragma unroll
            for (int k = 0; k < 4; k++) acc[i][j][k] = 0.f;

    auto load_stage = [&](int kt, int s) {
        const int k0 = kt * 32;
        const uint32_t sbase = sb + (uint32_t)(s * ST_TOTAL) * 2;
        {
            int r0a = row0 + ar0, r1a = row0 + ar1;
            int sz0 = (r0a < N_NODES) ? 16 : 0;
            int sz1 = (r1a < N_NODES) ? 16 : 0;
            size_t o0 = (size_t)min(r0a, N_NODES - 1) * DHID + k0 + as0;
            size_t o1 = (size_t)min(r1a, N_NODES - 1) * DHID + k0 + as1;
            cpa16(sbase + (ar0 * LDA + as0) * 2, Ah + o0, sz0);
            cpa16(sbase + (ar1 * LDA + as1) * 2, Ah + o1, sz1);
            cpa16(sbase + (OFF_AL + ar0 * LDA + as0) * 2, Al + o0, sz0);
            cpa16(sbase + (OFF_AL + ar1 * LDA + as1) * 2, Al + o1, sz1);
        }
        {
            size_t ob = (size_t)(col0 + br) * DHID + k0 + bs;
            cpa16(sbase + (OFF_BH + br * LDA + bs) * 2, Bh + ob, 16);
            cpa16(sbase + (OFF_BL + br * LDA + bs) * 2, Bl + ob, 16);
        }
        asm volatile("cp.async.commit_group;");
    };

    load_stage(0, 0);

    for (int kt = 0; kt < 8; kt++) {
        const int s = kt & 1;
        if (kt < 7) load_stage(kt + 1, s ^ 1);
        if (kt < 7) asm volatile("cp.async.wait_group 1;");
        else        asm volatile("cp.async.wait_group 0;");
        __syncthreads();

        const uint32_t stg = sb + (uint32_t)(s * ST_TOTAL) * 2;
        const uint32_t aBaseH = stg + (uint32_t)(aTerm + aTileOff) * 2;
        const uint32_t aBaseL = aBaseH + (uint32_t)ST_A * 2;
        const uint32_t bBaseH = stg + (uint32_t)(OFF_BH + bTerm + bTileOff) * 2;
        const uint32_t bBaseL = bBaseH + (uint32_t)ST_B * 2;

#pragma unroll
        for (int kk = 0; kk < 32; kk += 16) {
            uint32_t ah[4][4], al[4][4], bh[4][2], bl[4][2];
#pragma unroll
            for (int mt = 0; mt < 4; mt++) {
                uint32_t off = (uint32_t)(mt * 16 * LDA + kk) * 2;
                ldsm4(ah[mt], aBaseH + off);
                ldsm4(al[mt], aBaseL + off);
            }
#pragma unroll
            for (int p = 0; p < 2; p++) {
                uint32_t off = (uint32_t)(p * 16 * LDA + kk) * 2;
                uint32_t t[4];
                ldsm4(t, bBaseH + off);
                bh[2 * p][0] = t[0]; bh[2 * p][1] = t[1];
                bh[2 * p + 1][0] = t[2]; bh[2 * p + 1][1] = t[3];
                ldsm4(t, bBaseL + off);
                bl[2 * p][0] = t[0]; bl[2 * p][1] = t[1];
                bl[2 * p + 1][0] = t[2]; bl[2 * p + 1][1] = t[3];
            }
#pragma unroll
            for (int mt = 0; mt < 4; mt++)
#pragma unroll
                for (int nt = 0; nt < 4; nt++) {
                    mma_bf16(acc[mt][nt], ah[mt], bh[nt]);
                    mma_bf16(acc[mt][nt], ah[mt], bl[nt]);
                    mma_bf16(acc[mt][nt], al[mt], bh[nt]);
                }
        }
        __syncthreads();
    }

#pragma unroll
    for (int mt = 0; mt < 4; mt++) {
        int r0 = row0 + wm * 64 + mt * 16 + g;
#pragma unroll
        for (int half = 0; half < 2; half++) {
            int row = r0 + half * 8;
            if (row >= N_NODES) continue;
#pragma unroll
            for (int nt = 0; nt < 4; nt++) {
                int col = col0 + wn * 32 + nt * 8 + tg * 2;
                float c0 = acc[mt][nt][half * 2 + 0];
                float c1 = acc[mt][nt][half * 2 + 1];
                if (MODE == 0) {
                    c0 = fmaxf(c0 + __ldg(bias + col), 0.f);
                    c1 = fmaxf(c1 + __ldg(bias + col + 1), 0.f);
                    float h0 = __bfloat162float(__float2bfloat16_rn(c0));
                    float h1 = __bfloat162float(__float2bfloat16_rn(c1));
                    size_t o = (size_t)row * DHID + col;
                    *reinterpret_cast<uint32_t*>(Ch + o) = pack_bf16(h0, h1);
                    *reinterpret_cast<uint32_t*>(Cl + o) = pack_bf16(c0 - h0, c1 - h1);
                } else {
                    *reinterpret_cast<float2*>(C + (size_t)row * DHID + col) = make_float2(c0, c1);
                }
            }
        }
    }
}

// ---------------------------------------------------------------------------
extern "C" void kernel_launch(void* const* d_in, const int* in_sizes, int n_in,
                              void* d_out, int out_size) {
    const float* x   = (const float*)d_in[0];
    const int*   ei  = (const int*)d_in[1];
    const float* W1l = (const float*)d_in[2];
    const float* b1  = (const float*)d_in[3];
    const float* W1r = (const float*)d_in[4];
    const float* W2l = (const float*)d_in[5];
    const float* b2  = (const float*)d_in[6];
    const float* W2r = (const float*)d_in[7];
    float* out = (float*)d_out;

    const int E = in_sizes[1] / 2;
    const int* src = ei;
    const int* dst = ei + E;

    int *degi, *off, *cur, *esrc;
    float *pq;
    uint16_t *a1h, *a1l, *hh, *hl, *bh, *bl;
    cudaGetSymbolAddress((void**)&degi, g_degi);
    cudaGetSymbolAddress((void**)&off,  g_off);
    cudaGetSymbolAddress((void**)&cur,  g_cur);
    cudaGetSymbolAddress((void**)&esrc, g_esrc);
    cudaGetSymbolAddress((void**)&pq,   g_pq);
    cudaGetSymbolAddress((void**)&a1h,  g_a1h);
    cudaGetSymbolAddress((void**)&a1l,  g_a1l);
    cudaGetSymbolAddress((void**)&hh,   g_hh);
    cudaGetSymbolAddress((void**)&hl,   g_hl);
    cudaGetSymbolAddress((void**)&bh,   g_bh);
    cudaGetSymbolAddress((void**)&bl,   g_bl);

    const int SMEM = 2 * ST_TOTAL * 2;   // 122880 B
    static bool attr_done = false;
    if (!attr_done) {
        cudaFuncSetAttribute(gemm_mma<0>, cudaFuncAttributeMaxDynamicSharedMemorySize, SMEM);
        cudaFuncSetAttribute(gemm_mma<1>, cudaFuncAttributeMaxDynamicSharedMemorySize, SMEM);
        attr_done = true;
    }

    const dim3 GG((N_NODES + 255) / 256, 2);
    const int AGG_GRID = (N_NODES + 7) / 8;

    // CSR build
    zero_int_kernel<<<(N_NODES + 255) / 256, 256>>>(degi, N_NODES);
    degi_kernel<<<(E + 255) / 256, 256>>>(dst, E, degi);
    prefix_kernel<<<1, 1024>>>(degi, off, cur, E);
    fill_kernel<<<(E + 255) / 256, 256>>>(src, dst, off, cur, esrc, E);
    split_w_kernel<<<(2 * DHID * DHID / 4 + 255) / 256, 256>>>(W1l, W1r, W2l, W2r, bh, bl);

    // layer 1
    agg_csr_kernel<0><<<AGG_GRID, 256>>>(x, off, esrc, a1h, a1l, nullptr, nullptr);
    gemm_mma<0><<<GG, 512, SMEM>>>(a1h, a1l, bh, bl, b1, nullptr, hh, hl);

    // layer 2
    gemm_mma<1><<<GG, 512, SMEM>>>(hh, hl, bh + DHID * DHID, bl + DHID * DHID,
                                   nullptr, pq, nullptr, nullptr);
    agg_csr_kernel<1><<<AGG_GRID, 256>>>(pq, off, esrc, nullptr, nullptr, b2, out);
}

// round 9
// speedup vs baseline: 1.9169x; 1.0964x over previous
#include <cuda_runtime.h>
#include <cuda_fp16.h>
#include <cstdint>
#include <cstddef>

#define N_NODES 50000
#define DIN 128
#define DHID 256
#define E_MAX 1000000

// ---- scratch (static device globals; no allocation allowed) ----
__device__ int g_degi[N_NODES];
__device__ int g_off[N_NODES + 1];
__device__ int g_cur[N_NODES];
__device__ int g_esrc[E_MAX];
__device__ float g_pq[N_NODES * DHID];
__device__ uint16_t g_a1h[N_NODES * DHID], g_a1l[N_NODES * DHID];   // layer1 A split (fp16)
__device__ uint16_t g_hh[N_NODES * DHID],  g_hl[N_NODES * DHID];    // relu(h) split (fp16)
__device__ uint16_t g_wh[2 * DHID * DHID];                          // weights fp16

// ---------------------------------------------------------------------------
__device__ __forceinline__ uint32_t smem_u32(const void* p) {
    uint32_t a;
    asm("{ .reg .u64 t; cvta.to.shared.u64 t, %1; cvt.u32.u64 %0, t; }" : "=r"(a) : "l"(p));
    return a;
}
__device__ __forceinline__ uint32_t pack_f16(float x, float y) {
    __half2 t = __floats2half2_rn(x, y);
    return *reinterpret_cast<uint32_t*>(&t);
}
// fp16 two-term split of a float4
__device__ __forceinline__ void split4h(float4 v, uint32_t* hi2, uint32_t* lo2) {
    float hx = __half2float(__float2half_rn(v.x));
    float hy = __half2float(__float2half_rn(v.y));
    float hz = __half2float(__float2half_rn(v.z));
    float hw = __half2float(__float2half_rn(v.w));
    hi2[0] = pack_f16(hx, hy);
    hi2[1] = pack_f16(hz, hw);
    lo2[0] = pack_f16(v.x - hx, v.y - hy);
    lo2[1] = pack_f16(v.z - hz, v.w - hw);
}
__device__ __forceinline__ void cpa16(uint32_t saddr, const void* g, int sz) {
    asm volatile("cp.async.cg.shared.global [%0], [%1], 16, %2;" :: "r"(saddr), "l"(g), "r"(sz));
}
__device__ __forceinline__ void mma_f16(float* c, const uint32_t* a, const uint32_t* b) {
    asm volatile(
        "mma.sync.aligned.m16n8k16.row.col.f32.f16.f16.f32 "
        "{%0,%1,%2,%3}, {%4,%5,%6,%7}, {%8,%9}, {%0,%1,%2,%3};"
        : "+f"(c[0]), "+f"(c[1]), "+f"(c[2]), "+f"(c[3])
        : "r"(a[0]), "r"(a[1]), "r"(a[2]), "r"(a[3]), "r"(b[0]), "r"(b[1]));
}
__device__ __forceinline__ void ldsm4(uint32_t* r, uint32_t a) {
    asm volatile("ldmatrix.sync.aligned.m8n8.x4.shared.b16 {%0,%1,%2,%3}, [%4];"
                 : "=r"(r[0]), "=r"(r[1]), "=r"(r[2]), "=r"(r[3]) : "r"(a));
}

// ---------------------------------------------------------------------------
// CSR build
// ---------------------------------------------------------------------------
__global__ void zero_int_kernel(int* __restrict__ p, int n) {
    int i = blockIdx.x * blockDim.x + threadIdx.x;
    if (i < n) p[i] = 0;
}
__global__ void degi_kernel(const int* __restrict__ dst, int E, int* __restrict__ degi) {
    int i = blockIdx.x * blockDim.x + threadIdx.x;
    if (i < E) atomicAdd(&degi[dst[i]], 1);
}
__global__ __launch_bounds__(1024)
void prefix_kernel(const int* __restrict__ degi, int* __restrict__ off,
                   int* __restrict__ cur, int E) {
    __shared__ int part[1024];
    const int t = threadIdx.x;
    const int CH = (N_NODES + 1023) / 1024;
    const int base = t * CH;
    int s = 0;
#pragma unroll 4
    for (int i = 0; i < CH; i++) {
        int idx = base + i;
        if (idx < N_NODES) s += degi[idx];
    }
    part[t] = s;
    __syncthreads();
    for (int o = 1; o < 1024; o <<= 1) {
        int v = (t >= o) ? part[t - o] : 0;
        __syncthreads();
        part[t] += v;
        __syncthreads();
    }
    int run = (t == 0) ? 0 : part[t - 1];
#pragma unroll 4
    for (int i = 0; i < CH; i++) {
        int idx = base + i;
        if (idx < N_NODES) {
            off[idx] = run;
            run += degi[idx];
            cur[idx] = 0;
        }
    }
    if (t == 0) off[N_NODES] = E;
}
__global__ void fill_kernel(const int* __restrict__ src, const int* __restrict__ dst,
                            const int* __restrict__ off, int* __restrict__ cur,
                            int* __restrict__ esrc, int E) {
    int e = blockIdx.x * blockDim.x + threadIdx.x;
    if (e >= E) return;
    int d = dst[e];
    int p = atomicAdd(&cur[d], 1);
    esrc[off[d] + p] = src[e];
}

// ---------------------------------------------------------------------------
// weight convert (fp16 only): layer0 = [W1l | W1r] K-concat ; layer1 = [W2l ; W2r] N-concat
// ---------------------------------------------------------------------------
__global__ void conv_w_kernel(const float* __restrict__ W1l, const float* __restrict__ W1r,
                              const float* __restrict__ W2l, const float* __restrict__ W2r,
                              uint16_t* __restrict__ wh) {
    int t = blockIdx.x * blockDim.x + threadIdx.x;
    if (t >= 2 * DHID * DHID / 4) return;
    int layer = t >> 14;
    int e0 = (t & 16383) * 4;
    int j = e0 >> 8, k = e0 & 255;
    float4 v;
    if (layer == 0) {
        v = (k < DIN) ? *reinterpret_cast<const float4*>(W1l + (size_t)j * DIN + k)
                      : *reinterpret_cast<const float4*>(W1r + (size_t)j * DIN + (k - DIN));
    } else {
        v = (j < 128) ? *reinterpret_cast<const float4*>(W2l + (size_t)j * DHID + k)
                      : *reinterpret_cast<const float4*>(W2r + (size_t)(j - 128) * DHID + k);
    }
    size_t o = (size_t)layer * DHID * DHID + e0;
    *reinterpret_cast<uint32_t*>(wh + o)     = pack_f16(v.x, v.y);
    *reinterpret_cast<uint32_t*>(wh + o + 2) = pack_f16(v.z, v.w);
}

// ---------------------------------------------------------------------------
// CSR aggregation (near LTS-read floor)
// ---------------------------------------------------------------------------
template <int MODE>
__global__ __launch_bounds__(256)
void agg_csr_kernel(const float* __restrict__ feat,
                    const int* __restrict__ off, const int* __restrict__ esrc,
                    uint16_t* __restrict__ ah, uint16_t* __restrict__ al,
                    const float* __restrict__ b2, float* __restrict__ out) {
    const int d = blockIdx.x * 8 + (threadIdx.x >> 5);
    if (d >= N_NODES) return;
    const int lane = threadIdx.x & 31;
    const int LD4 = (MODE == 0) ? (DIN / 4) : (DHID / 4);
    const float4* F = reinterpret_cast<const float4*>(feat);

    const int beg = __ldg(off + d);
    const int end = __ldg(off + d + 1);

    float4 a0 = make_float4(0.f, 0.f, 0.f, 0.f), a1 = a0, a2 = a0, a3 = a0;
    int i = beg;
    for (; i + 4 <= end; i += 4) {
        int s0 = __ldg(esrc + i), s1 = __ldg(esrc + i + 1);
        int s2 = __ldg(esrc + i + 2), s3 = __ldg(esrc + i + 3);
        float4 v0 = __ldg(F + (size_t)s0 * LD4 + lane);
        float4 v1 = __ldg(F + (size_t)s1 * LD4 + lane);
        float4 v2 = __ldg(F + (size_t)s2 * LD4 + lane);
        float4 v3 = __ldg(F + (size_t)s3 * LD4 + lane);
        a0.x += v0.x; a0.y += v0.y; a0.z += v0.z; a0.w += v0.w;
        a1.x += v1.x; a1.y += v1.y; a1.z += v1.z; a1.w += v1.w;
        a2.x += v2.x; a2.y += v2.y; a2.z += v2.z; a2.w += v2.w;
        a3.x += v3.x; a3.y += v3.y; a3.z += v3.z; a3.w += v3.w;
    }
    for (; i < end; i++) {
        int s = __ldg(esrc + i);
        float4 v = __ldg(F + (size_t)s * LD4 + lane);
        a0.x += v.x; a0.y += v.y; a0.z += v.z; a0.w += v.w;
    }
    float4 acc;
    acc.x = (a0.x + a1.x) + (a2.x + a3.x);
    acc.y = (a0.y + a1.y) + (a2.y + a3.y);
    acc.z = (a0.z + a1.z) + (a2.z + a3.z);
    acc.w = (a0.w + a1.w) + (a2.w + a3.w);

    const float rd = 1.0f / (float)max(end - beg, 1);
    acc.x *= rd; acc.y *= rd; acc.z *= rd; acc.w *= rd;

    if (MODE == 0) {
        uint32_t hi2[2], lo2[2];
        size_t o = (size_t)d * DHID + lane * 4;
        split4h(acc, hi2, lo2);
        *reinterpret_cast<uint32_t*>(ah + o)     = hi2[0];
        *reinterpret_cast<uint32_t*>(ah + o + 2) = hi2[1];
        *reinterpret_cast<uint32_t*>(al + o)     = lo2[0];
        *reinterpret_cast<uint32_t*>(al + o + 2) = lo2[1];
        float4 xv = __ldg(F + (size_t)d * LD4 + lane);
        split4h(xv, hi2, lo2);
        o += DIN;
        *reinterpret_cast<uint32_t*>(ah + o)     = hi2[0];
        *reinterpret_cast<uint32_t*>(ah + o + 2) = hi2[1];
        *reinterpret_cast<uint32_t*>(al + o)     = lo2[0];
        *reinterpret_cast<uint32_t*>(al + o + 2) = lo2[1];
    } else {
        float4 qv = __ldg(F + (size_t)d * LD4 + (DIN / 4) + lane);
        float4 bb = __ldg(reinterpret_cast<const float4*>(b2) + lane);
        float4 o;
        o.x = acc.x + qv.x + bb.x;
        o.y = acc.y + qv.y + bb.y;
        o.z = acc.z + qv.z + bb.z;
        o.w = acc.w + qv.w + bb.w;
        reinterpret_cast<float4*>(out)[(size_t)d * (DIN / 4) + lane] = o;
    }
}

// ---------------------------------------------------------------------------
// fp16 2-term split GEMM: C = (Ah + Al) @ Bh^T, 256x128 tile, 512 threads
// ---------------------------------------------------------------------------
#define LDA 40
#define ST_A (256 * LDA)                 // 10240 elems per A array per stage
#define ST_B (128 * LDA)                 // 5120 elems per B array per stage
#define ST_TOTAL (2 * ST_A + ST_B)       // 25600 elems per stage
#define OFF_AL ST_A
#define OFF_BH (2 * ST_A)

template <int MODE>
__global__ __launch_bounds__(512, 1)
void gemm_mma(const uint16_t* __restrict__ Ah, const uint16_t* __restrict__ Al,
              const uint16_t* __restrict__ Bh,
              const float* __restrict__ bias,
              float* __restrict__ C, uint16_t* __restrict__ Ch, uint16_t* __restrict__ Cl) {
    extern __shared__ __align__(16) uint16_t smem[];
    const uint32_t sb = smem_u32(smem);

    const int tid  = threadIdx.x;
    const int wid  = tid >> 5;
    const int lane = tid & 31;
    const int g    = lane >> 2;
    const int tg   = lane & 3;
    const int row0 = blockIdx.x * 256;
    const int col0 = blockIdx.y * 128;
    const int wm   = wid >> 2;
    const int wn   = wid & 3;

    // cp.async maps: A chunks q = tid*2, tid*2+1 (0..1023); B chunk q = tid (0..511)
    const int qa0 = tid * 2;
    const int ar0 = qa0 >> 2, as0 = (qa0 & 3) * 8;
    const int ar1 = (qa0 + 1) >> 2, as1 = ((qa0 + 1) & 3) * 8;
    const int br = tid >> 2, bs = (tid & 3) * 8;

    const int aTerm = (lane & 15) * LDA + (lane >> 4) * 8;
    const int bTerm = ((lane & 7) + ((lane >> 4) << 3)) * LDA + ((lane >> 3) & 1) * 8;
    const int aTileOff = (wm * 64) * LDA;
    const int bTileOff = (wn * 32) * LDA;

    float acc[4][4][4];
#pragma unroll
    for (int i = 0; i < 4; i++)
#pragma unroll
        for (int j = 0; j < 4; j++)
#pragma unroll
            for (int k = 0; k < 4; k++) acc[i][j][k] = 0.f;

    auto load_stage = [&](int kt, int s) {
        const int k0 = kt * 32;
        const uint32_t sbase = sb + (uint32_t)(s * ST_TOTAL) * 2;
        {
            int r0a = row0 + ar0, r1a = row0 + ar1;
            int sz0 = (r0a < N_NODES) ? 16 : 0;
            int sz1 = (r1a < N_NODES) ? 16 : 0;
            size_t o0 = (size_t)min(r0a, N_NODES - 1) * DHID + k0 + as0;
            size_t o1 = (size_t)min(r1a, N_NODES - 1) * DHID + k0 + as1;
            cpa16(sbase + (ar0 * LDA + as0) * 2, Ah + o0, sz0);
            cpa16(sbase + (ar1 * LDA + as1) * 2, Ah + o1, sz1);
            cpa16(sbase + (OFF_AL + ar0 * LDA + as0) * 2, Al + o0, sz0);
            cpa16(sbase + (OFF_AL + ar1 * LDA + as1) * 2, Al + o1, sz1);
        }
        {
            size_t ob = (size_t)(col0 + br) * DHID + k0 + bs;
            cpa16(sbase + (OFF_BH + br * LDA + bs) * 2, Bh + ob, 16);
        }
        asm volatile("cp.async.commit_group;");
    };

    load_stage(0, 0);

    for (int kt = 0; kt < 8; kt++) {
        const int s = kt & 1;
        if (kt < 7) load_stage(kt + 1, s ^ 1);
        if (kt < 7) asm volatile("cp.async.wait_group 1;");
        else        asm volatile("cp.async.wait_group 0;");
        __syncthreads();

        const uint32_t stg = sb + (uint32_t)(s * ST_TOTAL) * 2;
        const uint32_t aBaseH = stg + (uint32_t)(aTerm + aTileOff) * 2;
        const uint32_t aBaseL = aBaseH + (uint32_t)ST_A * 2;
        const uint32_t bBaseH = stg + (uint32_t)(OFF_BH + bTerm + bTileOff) * 2;

#pragma unroll
        for (int kk = 0; kk < 32; kk += 16) {
            uint32_t ah[4][4], al[4][4], bh[4][2];
#pragma unroll
            for (int mt = 0; mt < 4; mt++) {
                uint32_t off = (uint32_t)(mt * 16 * LDA + kk) * 2;
                ldsm4(ah[mt], aBaseH + off);
                ldsm4(al[mt], aBaseL + off);
            }
#pragma unroll
            for (int p = 0; p < 2; p++) {
                uint32_t off = (uint32_t)(p * 16 * LDA + kk) * 2;
                uint32_t t[4];
                ldsm4(t, bBaseH + off);
                bh[2 * p][0] = t[0]; bh[2 * p][1] = t[1];
                bh[2 * p + 1][0] = t[2]; bh[2 * p + 1][1] = t[3];
            }
#pragma unroll
            for (int mt = 0; mt < 4; mt++)
#pragma unroll
                for (int nt = 0; nt < 4; nt++) {
                    mma_f16(acc[mt][nt], ah[mt], bh[nt]);
                    mma_f16(acc[mt][nt], al[mt], bh[nt]);
                }
        }
        __syncthreads();
    }

#pragma unroll
    for (int mt = 0; mt < 4; mt++) {
        int r0 = row0 + wm * 64 + mt * 16 + g;
#pragma unroll
        for (int half = 0; half < 2; half++) {
            int row = r0 + half * 8;
            if (row >= N_NODES) continue;
#pragma unroll
            for (int nt = 0; nt < 4; nt++) {
                int col = col0 + wn * 32 + nt * 8 + tg * 2;
                float c0 = acc[mt][nt][half * 2 + 0];
                float c1 = acc[mt][nt][half * 2 + 1];
                if (MODE == 0) {
                    c0 = fmaxf(c0 + __ldg(bias + col), 0.f);
                    c1 = fmaxf(c1 + __ldg(bias + col + 1), 0.f);
                    float h0 = __half2float(__float2half_rn(c0));
                    float h1 = __half2float(__float2half_rn(c1));
                    size_t o = (size_t)row * DHID + col;
                    *reinterpret_cast<uint32_t*>(Ch + o) = pack_f16(h0, h1);
                    *reinterpret_cast<uint32_t*>(Cl + o) = pack_f16(c0 - h0, c1 - h1);
                } else {
                    *reinterpret_cast<float2*>(C + (size_t)row * DHID + col) = make_float2(c0, c1);
                }
            }
        }
    }
}

// ---------------------------------------------------------------------------
extern "C" void kernel_launch(void* const* d_in, const int* in_sizes, int n_in,
                              void* d_out, int out_size) {
    const float* x   = (const float*)d_in[0];
    const int*   ei  = (const int*)d_in[1];
    const float* W1l = (const float*)d_in[2];
    const float* b1  = (const float*)d_in[3];
    const float* W1r = (const float*)d_in[4];
    const float* W2l = (const float*)d_in[5];
    const float* b2  = (const float*)d_in[6];
    const float* W2r = (const float*)d_in[7];
    float* out = (float*)d_out;

    const int E = in_sizes[1] / 2;
    const int* src = ei;
    const int* dst = ei + E;

    int *degi, *off, *cur, *esrc;
    float *pq;
    uint16_t *a1h, *a1l, *hh, *hl, *wh;
    cudaGetSymbolAddress((void**)&degi, g_degi);
    cudaGetSymbolAddress((void**)&off,  g_off);
    cudaGetSymbolAddress((void**)&cur,  g_cur);
    cudaGetSymbolAddress((void**)&esrc, g_esrc);
    cudaGetSymbolAddress((void**)&pq,   g_pq);
    cudaGetSymbolAddress((void**)&a1h,  g_a1h);
    cudaGetSymbolAddress((void**)&a1l,  g_a1l);
    cudaGetSymbolAddress((void**)&hh,   g_hh);
    cudaGetSymbolAddress((void**)&hl,   g_hl);
    cudaGetSymbolAddress((void**)&wh,   g_wh);

    const int SMEM = 2 * ST_TOTAL * 2;   // 102400 B
    static bool attr_done = false;
    if (!attr_done) {
        cudaFuncSetAttribute(gemm_mma<0>, cudaFuncAttributeMaxDynamicSharedMemorySize, SMEM);
        cudaFuncSetAttribute(gemm_mma<1>, cudaFuncAttributeMaxDynamicSharedMemorySize, SMEM);
        attr_done = true;
    }

    const dim3 GG((N_NODES + 255) / 256, 2);
    const int AGG_GRID = (N_NODES + 7) / 8;

    // CSR build + weight convert
    zero_int_kernel<<<(N_NODES + 255) / 256, 256>>>(degi, N_NODES);
    degi_kernel<<<(E + 255) / 256, 256>>>(dst, E, degi);
    prefix_kernel<<<1, 1024>>>(degi, off, cur, E);
    fill_kernel<<<(E + 255) / 256, 256>>>(src, dst, off, cur, esrc, E);
    conv_w_kernel<<<(2 * DHID * DHID / 4 + 255) / 256, 256>>>(W1l, W1r, W2l, W2r, wh);

    // layer 1
    agg_csr_kernel<0><<<AGG_GRID, 256>>>(x, off, esrc, a1h, a1l, nullptr, nullptr);
    gemm_mma<0><<<GG, 512, SMEM>>>(a1h, a1l, wh, b1, nullptr, hh, hl);

    // layer 2
    gemm_mma<1><<<GG, 512, SMEM>>>(hh, hl, wh + DHID * DHID, nullptr, pq, nullptr, nullptr);
    agg_csr_kernel<1><<<AGG_GRID, 256>>>(pq, off, esrc, nullptr, nullptr, b2, out);
}

// round 10
// speedup vs baseline: 2.3448x; 1.2232x over previous
#include <cuda_runtime.h>
#include <cuda_fp16.h>
#include <cstdint>
#include <cstddef>

#define N_NODES 50000
#define DIN 128
#define DHID 256
#define E_MAX 1000000

// ---- scratch (static device globals; no allocation allowed) ----
__device__ int g_degi[N_NODES];
__device__ int g_off[N_NODES + 1];
__device__ int g_cur[N_NODES];
__device__ int g_esrc[E_MAX];
__device__ uint16_t g_x16[N_NODES * DIN];      // x in fp16
__device__ uint16_t g_a1[N_NODES * DHID];      // layer1 A = [mean | x] fp16
__device__ uint16_t g_h16[N_NODES * DHID];     // relu(h) fp16
__device__ uint16_t g_p16[N_NODES * DIN];      // p = h@W2l^T fp16
__device__ float    g_q[N_NODES * DIN];        // q = h@W2r^T fp32
__device__ uint16_t g_wh[2 * DHID * DHID];     // weights fp16

// ---------------------------------------------------------------------------
__device__ __forceinline__ uint32_t smem_u32(const void* p) {
    uint32_t a;
    asm("{ .reg .u64 t; cvta.to.shared.u64 t, %1; cvt.u32.u64 %0, t; }" : "=r"(a) : "l"(p));
    return a;
}
__device__ __forceinline__ uint32_t pack_f16(float x, float y) {
    __half2 t = __floats2half2_rn(x, y);
    return *reinterpret_cast<uint32_t*>(&t);
}
__device__ __forceinline__ void cpa16(uint32_t saddr, const void* g, int sz) {
    asm volatile("cp.async.cg.shared.global [%0], [%1], 16, %2;" :: "r"(saddr), "l"(g), "r"(sz));
}
__device__ __forceinline__ void mma_f16(float* c, const uint32_t* a, const uint32_t* b) {
    asm volatile(
        "mma.sync.aligned.m16n8k16.row.col.f32.f16.f16.f32 "
        "{%0,%1,%2,%3}, {%4,%5,%6,%7}, {%8,%9}, {%0,%1,%2,%3};"
        : "+f"(c[0]), "+f"(c[1]), "+f"(c[2]), "+f"(c[3])
        : "r"(a[0]), "r"(a[1]), "r"(a[2]), "r"(a[3]), "r"(b[0]), "r"(b[1]));
}
__device__ __forceinline__ void ldsm4(uint32_t* r, uint32_t a) {
    asm volatile("ldmatrix.sync.aligned.m8n8.x4.shared.b16 {%0,%1,%2,%3}, [%4];"
                 : "=r"(r[0]), "=r"(r[1]), "=r"(r[2]), "=r"(r[3]) : "r"(a));
}
__device__ __forceinline__ void acc_u2(float4& a, uint2 u) {
    float2 lo = __half22float2(*reinterpret_cast<__half2*>(&u.x));
    float2 hi = __half22float2(*reinterpret_cast<__half2*>(&u.y));
    a.x += lo.x; a.y += lo.y; a.z += hi.x; a.w += hi.y;
}

// ---------------------------------------------------------------------------
// CSR build
// ---------------------------------------------------------------------------
__global__ void zero_int_kernel(int* __restrict__ p, int n) {
    int i = blockIdx.x * blockDim.x + threadIdx.x;
    if (i < n) p[i] = 0;
}
__global__ void degi_kernel(const int* __restrict__ dst, int E, int* __restrict__ degi) {
    int i = blockIdx.x * blockDim.x + threadIdx.x;
    if (i < E) atomicAdd(&degi[dst[i]], 1);
}
__global__ __launch_bounds__(1024)
void prefix_kernel(const int* __restrict__ degi, int* __restrict__ off,
                   int* __restrict__ cur, int E) {
    __shared__ int part[1024];
    const int t = threadIdx.x;
    const int CH = (N_NODES + 1023) / 1024;
    const int base = t * CH;
    int s = 0;
#pragma unroll 4
    for (int i = 0; i < CH; i++) {
        int idx = base + i;
        if (idx < N_NODES) s += degi[idx];
    }
    part[t] = s;
    __syncthreads();
    for (int o = 1; o < 1024; o <<= 1) {
        int v = (t >= o) ? part[t - o] : 0;
        __syncthreads();
        part[t] += v;
        __syncthreads();
    }
    int run = (t == 0) ? 0 : part[t - 1];
#pragma unroll 4
    for (int i = 0; i < CH; i++) {
        int idx = base + i;
        if (idx < N_NODES) {
            off[idx] = run;
            run += degi[idx];
            cur[idx] = 0;
        }
    }
    if (t == 0) off[N_NODES] = E;
}
__global__ void fill_kernel(const int* __restrict__ src, const int* __restrict__ dst,
                            const int* __restrict__ off, int* __restrict__ cur,
                            int* __restrict__ esrc, int E) {
    int e = blockIdx.x * blockDim.x + threadIdx.x;
    if (e >= E) return;
    int d = dst[e];
    int p = atomicAdd(&cur[d], 1);
    esrc[off[d] + p] = src[e];
}

// ---------------------------------------------------------------------------
// converts: weights -> fp16 concat layouts ; x -> fp16
// ---------------------------------------------------------------------------
__global__ void conv_w_kernel(const float* __restrict__ W1l, const float* __restrict__ W1r,
                              const float* __restrict__ W2l, const float* __restrict__ W2r,
                              uint16_t* __restrict__ wh) {
    int t = blockIdx.x * blockDim.x + threadIdx.x;
    if (t >= 2 * DHID * DHID / 4) return;
    int layer = t >> 14;
    int e0 = (t & 16383) * 4;
    int j = e0 >> 8, k = e0 & 255;
    float4 v;
    if (layer == 0) {
        v = (k < DIN) ? *reinterpret_cast<const float4*>(W1l + (size_t)j * DIN + k)
                      : *reinterpret_cast<const float4*>(W1r + (size_t)j * DIN + (k - DIN));
    } else {
        v = (j < 128) ? *reinterpret_cast<const float4*>(W2l + (size_t)j * DHID + k)
                      : *reinterpret_cast<const float4*>(W2r + (size_t)(j - 128) * DHID + k);
    }
    size_t o = (size_t)layer * DHID * DHID + e0;
    *reinterpret_cast<uint32_t*>(wh + o)     = pack_f16(v.x, v.y);
    *reinterpret_cast<uint32_t*>(wh + o + 2) = pack_f16(v.z, v.w);
}

__global__ void conv_x_kernel(const float* __restrict__ x, uint16_t* __restrict__ x16) {
    int t = blockIdx.x * blockDim.x + threadIdx.x;
    if (t >= N_NODES * DIN / 4) return;
    float4 v = *reinterpret_cast<const float4*>(x + (size_t)t * 4);
    uint2 o;
    o.x = pack_f16(v.x, v.y);
    o.y = pack_f16(v.z, v.w);
    reinterpret_cast<uint2*>(x16)[t] = o;
}

// ---------------------------------------------------------------------------
// CSR aggregation over fp16 features, one warp per node, 4-edge unroll.
// MODE 0: feat16 = x16 (ld 128). epilogue: A1 = [mean | x16] fp16
// MODE 1: feat16 = p16 (ld 128). epilogue: out = mean + q + b2 (fp32)
// ---------------------------------------------------------------------------
template <int MODE>
__global__ __launch_bounds__(256)
void agg_csr_kernel(const uint16_t* __restrict__ feat16,
                    const int* __restrict__ off, const int* __restrict__ esrc,
                    uint16_t* __restrict__ a1,
                    const float* __restrict__ q, const float* __restrict__ b2,
                    float* __restrict__ out) {
    const int d = blockIdx.x * 8 + (threadIdx.x >> 5);
    if (d >= N_NODES) return;
    const int lane = threadIdx.x & 31;
    const uint2* F = reinterpret_cast<const uint2*>(feat16);   // 32 uint2 per row

    const int beg = __ldg(off + d);
    const int end = __ldg(off + d + 1);

    float4 a0 = make_float4(0.f, 0.f, 0.f, 0.f), a1v = a0, a2 = a0, a3 = a0;
    int i = beg;
    for (; i + 4 <= end; i += 4) {
        int s0 = __ldg(esrc + i), s1 = __ldg(esrc + i + 1);
        int s2 = __ldg(esrc + i + 2), s3 = __ldg(esrc + i + 3);
        uint2 u0 = __ldg(F + (size_t)s0 * 32 + lane);
        uint2 u1 = __ldg(F + (size_t)s1 * 32 + lane);
        uint2 u2 = __ldg(F + (size_t)s2 * 32 + lane);
        uint2 u3 = __ldg(F + (size_t)s3 * 32 + lane);
        acc_u2(a0, u0); acc_u2(a1v, u1); acc_u2(a2, u2); acc_u2(a3, u3);
    }
    for (; i < end; i++) {
        int s = __ldg(esrc + i);
        uint2 u = __ldg(F + (size_t)s * 32 + lane);
        acc_u2(a0, u);
    }
    float4 acc;
    acc.x = (a0.x + a1v.x) + (a2.x + a3.x);
    acc.y = (a0.y + a1v.y) + (a2.y + a3.y);
    acc.z = (a0.z + a1v.z) + (a2.z + a3.z);
    acc.w = (a0.w + a1v.w) + (a2.w + a3.w);

    const float rd = 1.0f / (float)max(end - beg, 1);
    acc.x *= rd; acc.y *= rd; acc.z *= rd; acc.w *= rd;

    if (MODE == 0) {
        uint2 o;
        o.x = pack_f16(acc.x, acc.y);
        o.y = pack_f16(acc.z, acc.w);
        reinterpret_cast<uint2*>(a1 + (size_t)d * DHID)[lane] = o;
        // self x (already fp16) -> cols 128..255
        uint2 xv = __ldg(F + (size_t)d * 32 + lane);
        reinterpret_cast<uint2*>(a1 + (size_t)d * DHID + DIN)[lane] = xv;
    } else {
        float4 qv = __ldg(reinterpret_cast<const float4*>(q) + (size_t)d * 32 + lane);
        float4 bb = __ldg(reinterpret_cast<const float4*>(b2) + lane);
        float4 o;
        o.x = acc.x + qv.x + bb.x;
        o.y = acc.y + qv.y + bb.y;
        o.z = acc.z + qv.z + bb.z;
        o.w = acc.w + qv.w + bb.w;
        reinterpret_cast<float4*>(out)[(size_t)d * 32 + lane] = o;
    }
}

// ---------------------------------------------------------------------------
// fp16 GEMM: C = A @ B^T, 256x128 tile, 512 threads, cp.async double buffer.
// MODE 0: epilogue relu(+bias) -> fp16 Ch (ld 256)
// MODE 1: epilogue split: col0==0 -> fp16 p16 (ld 128); col0==128 -> fp32 q (ld 128)
// ---------------------------------------------------------------------------
#define LDA 40
#define ST_A (256 * LDA)                 // 10240 elems per stage
#define ST_B (128 * LDA)                 // 5120 elems per stage
#define ST_TOTAL (ST_A + ST_B)           // 15360 elems per stage
#define OFF_BH ST_A

template <int MODE>
__global__ __launch_bounds__(512, 1)
void gemm_mma(const uint16_t* __restrict__ Ah, const uint16_t* __restrict__ Bh,
              const float* __restrict__ bias,
              uint16_t* __restrict__ Ch, float* __restrict__ Cq) {
    extern __shared__ __align__(16) uint16_t smem[];
    const uint32_t sb = smem_u32(smem);

    const int tid  = threadIdx.x;
    const int wid  = tid >> 5;
    const int lane = tid & 31;
    const int g    = lane >> 2;
    const int tg   = lane & 3;
    const int row0 = blockIdx.x * 256;
    const int col0 = blockIdx.y * 128;
    const int wm   = wid >> 2;
    const int wn   = wid & 3;

    // cp.async maps: A chunks q = tid*2, tid*2+1 (0..1023); B chunk q = tid (0..511)
    const int qa0 = tid * 2;
    const int ar0 = qa0 >> 2, as0 = (qa0 & 3) * 8;
    const int ar1 = (qa0 + 1) >> 2, as1 = ((qa0 + 1) & 3) * 8;
    const int br = tid >> 2, bs = (tid & 3) * 8;

    const int aTerm = (lane & 15) * LDA + (lane >> 4) * 8;
    const int bTerm = ((lane & 7) + ((lane >> 4) << 3)) * LDA + ((lane >> 3) & 1) * 8;
    const int aTileOff = (wm * 64) * LDA;
    const int bTileOff = (wn * 32) * LDA;

    float acc[4][4][4];
#pragma unroll
    for (int i = 0; i < 4; i++)
#pragma unroll
        for (int j = 0; j < 4; j++)
#pragma unroll
            for (int k = 0; k < 4; k++) acc[i][j][k] = 0.f;

    auto load_stage = [&](int kt, int s) {
        const int k0 = kt * 32;
        const uint32_t sbase = sb + (uint32_t)(s * ST_TOTAL) * 2;
        {
            int r0a = row0 + ar0, r1a = row0 + ar1;
            int sz0 = (r0a < N_NODES) ? 16 : 0;
            int sz1 = (r1a < N_NODES) ? 16 : 0;
            size_t o0 = (size_t)min(r0a, N_NODES - 1) * DHID + k0 + as0;
            size_t o1 = (size_t)min(r1a, N_NODES - 1) * DHID + k0 + as1;
            cpa16(sbase + (ar0 * LDA + as0) * 2, Ah + o0, sz0);
            cpa16(sbase + (ar1 * LDA + as1) * 2, Ah + o1, sz1);
        }
        {
            size_t ob = (size_t)(col0 + br) * DHID + k0 + bs;
            cpa16(sbase + (OFF_BH + br * LDA + bs) * 2, Bh + ob, 16);
        }
        asm volatile("cp.async.commit_group;");
    };

    load_stage(0, 0);

    for (int kt = 0; kt < 8; kt++) {
        const int s = kt & 1;
        if (kt < 7) load_stage(kt + 1, s ^ 1);
        if (kt < 7) asm volatile("cp.async.wait_group 1;");
        else        asm volatile("cp.async.wait_group 0;");
        __syncthreads();

        const uint32_t stg = sb + (uint32_t)(s * ST_TOTAL) * 2;
        const uint32_t aBase = stg + (uint32_t)(aTerm + aTileOff) * 2;
        const uint32_t bBase = stg + (uint32_t)(OFF_BH + bTerm + bTileOff) * 2;

#pragma unroll
        for (int kk = 0; kk < 32; kk += 16) {
            uint32_t ah[4][4], bh[4][2];
#pragma unroll
            for (int mt = 0; mt < 4; mt++) {
                uint32_t off = (uint32_t)(mt * 16 * LDA + kk) * 2;
                ldsm4(ah[mt], aBase + off);
            }
#pragma unroll
            for (int p = 0; p < 2; p++) {
                uint32_t off = (uint32_t)(p * 16 * LDA + kk) * 2;
                uint32_t t[4];
                ldsm4(t, bBase + off);
                bh[2 * p][0] = t[0]; bh[2 * p][1] = t[1];
                bh[2 * p + 1][0] = t[2]; bh[2 * p + 1][1] = t[3];
            }
#pragma unroll
            for (int mt = 0; mt < 4; mt++)
#pragma unroll
                for (int nt = 0; nt < 4; nt++)
                    mma_f16(acc[mt][nt], ah[mt], bh[nt]);
        }
        __syncthreads();
    }

#pragma unroll
    for (int mt = 0; mt < 4; mt++) {
        int r0 = row0 + wm * 64 + mt * 16 + g;
#pragma unroll
        for (int half = 0; half < 2; half++) {
            int row = r0 + half * 8;
            if (row >= N_NODES) continue;
#pragma unroll
            for (int nt = 0; nt < 4; nt++) {
                int col = col0 + wn * 32 + nt * 8 + tg * 2;
                float c0 = acc[mt][nt][half * 2 + 0];
                float c1 = acc[mt][nt][half * 2 + 1];
                if (MODE == 0) {
                    c0 = fmaxf(c0 + __ldg(bias + col), 0.f);
                    c1 = fmaxf(c1 + __ldg(bias + col + 1), 0.f);
                    *reinterpret_cast<uint32_t*>(Ch + (size_t)row * DHID + col) = pack_f16(c0, c1);
                } else {
                    if (col0 == 0) {
                        *reinterpret_cast<uint32_t*>(Ch + (size_t)row * DIN + col) = pack_f16(c0, c1);
                    } else {
                        *reinterpret_cast<float2*>(Cq + (size_t)row * DIN + (col - 128)) =
                            make_float2(c0, c1);
                    }
                }
            }
        }
    }
}

// ---------------------------------------------------------------------------
extern "C" void kernel_launch(void* const* d_in, const int* in_sizes, int n_in,
                              void* d_out, int out_size) {
    const float* x   = (const float*)d_in[0];
    const int*   ei  = (const int*)d_in[1];
    const float* W1l = (const float*)d_in[2];
    const float* b1  = (const float*)d_in[3];
    const float* W1r = (const float*)d_in[4];
    const float* W2l = (const float*)d_in[5];
    const float* b2  = (const float*)d_in[6];
    const float* W2r = (const float*)d_in[7];
    float* out = (float*)d_out;

    const int E = in_sizes[1] / 2;
    const int* src = ei;
    const int* dst = ei + E;

    int *degi, *off, *cur, *esrc;
    float *q;
    uint16_t *x16, *a1, *h16, *p16, *wh;
    cudaGetSymbolAddress((void**)&degi, g_degi);
    cudaGetSymbolAddress((void**)&off,  g_off);
    cudaGetSymbolAddress((void**)&cur,  g_cur);
    cudaGetSymbolAddress((void**)&esrc, g_esrc);
    cudaGetSymbolAddress((void**)&x16,  g_x16);
    cudaGetSymbolAddress((void**)&a1,   g_a1);
    cudaGetSymbolAddress((void**)&h16,  g_h16);
    cudaGetSymbolAddress((void**)&p16,  g_p16);
    cudaGetSymbolAddress((void**)&q,    g_q);
    cudaGetSymbolAddress((void**)&wh,   g_wh);

    const int SMEM = 2 * ST_TOTAL * 2;   // 61440 B
    static bool attr_done = false;
    if (!attr_done) {
        cudaFuncSetAttribute(gemm_mma<0>, cudaFuncAttributeMaxDynamicSharedMemorySize, SMEM);
        cudaFuncSetAttribute(gemm_mma<1>, cudaFuncAttributeMaxDynamicSharedMemorySize, SMEM);
        attr_done = true;
    }

    const dim3 GG((N_NODES + 255) / 256, 2);
    const int AGG_GRID = (N_NODES + 7) / 8;

    // CSR build + converts
    zero_int_kernel<<<(N_NODES + 255) / 256, 256>>>(degi, N_NODES);
    degi_kernel<<<(E + 255) / 256, 256>>>(dst, E, degi);
    conv_w_kernel<<<(2 * DHID * DHID / 4 + 255) / 256, 256>>>(W1l, W1r, W2l, W2r, wh);
    conv_x_kernel<<<(N_NODES * DIN / 4 + 255) / 256, 256>>>(x, x16);
    prefix_kernel<<<1, 1024>>>(degi, off, cur, E);
    fill_kernel<<<(E + 255) / 256, 256>>>(src, dst, off, cur, esrc, E);

    // layer 1
    agg_csr_kernel<0><<<AGG_GRID, 256>>>(x16, off, esrc, a1, nullptr, nullptr, nullptr);
    gemm_mma<0><<<GG, 512, SMEM>>>(a1, wh, b1, h16, nullptr);

    // layer 2
    gemm_mma<1><<<GG, 512, SMEM>>>(h16, wh + DHID * DHID, nullptr, p16, q);
    agg_csr_kernel<1><<<AGG_GRID, 256>>>(p16, off, esrc, nullptr, q, b2, out);
}